// round 7
// baseline (speedup 1.0000x reference)
#include <cuda_runtime.h>
#include <cstdint>

typedef unsigned long long ull;

#define OUT_ROWS 4099
#define OPSTR (8*6*1024*16)
#define SCALE 0.2773500981126146f
#define L2E   1.4426950408889634f
#define NL2E  (-1.4426950408889634f)
#define CQ    (SCALE*L2E)
#define TKEYS 128
#define NUNITS 384
#define NBLK 152

// scratch (device globals; no allocations allowed)
__device__ float g_Q[4*OPSTR];   // [op][b][h][i][16]
__device__ float g_K[4*OPSTR];   // [op][b][h][pair][dim][2]  pair-interleaved
__device__ float g_V[4*OPSTR];   // same layout; dim13 lane := 1.0 (Z trick)
__device__ float g_tok[8*3*78];
__device__ int   g_ctr;

struct PtrPack {
    const float* x; const float* y; const float* z;
    const float* W[12];   // 0..3 Q(tv,ta,ctv,cta), 4..7 K, 8..11 V
};

__device__ __forceinline__ float ex2(float v) {
    float r; asm("ex2.approx.ftz.f32 %0, %1;" : "=f"(r) : "f"(v)); return r;
}
__device__ __forceinline__ float lg2(float v) {
    float r; asm("lg2.approx.ftz.f32 %0, %1;" : "=f"(r) : "f"(v)); return r;
}
__device__ __forceinline__ ull pk(float lo, float hi) {
    ull r; asm("mov.b64 %0, {%1,%2};" : "=l"(r) : "f"(lo), "f"(hi)); return r;
}
__device__ __forceinline__ void upk(ull v, float& lo, float& hi) {
    asm("mov.b64 {%0,%1}, %2;" : "=f"(lo), "=f"(hi) : "l"(v));
}
__device__ __forceinline__ ull fma2(ull a, ull b, ull c) {
    ull d; asm("fma.rn.f32x2 %0, %1, %2, %3;" : "=l"(d) : "l"(a), "l"(b), "l"(c)); return d;
}
__device__ __forceinline__ ull add2(ull a, ull b) {
    ull d; asm("add.rn.f32x2 %0, %1, %2;" : "=l"(d) : "l"(a), "l"(b)); return d;
}
__device__ __forceinline__ void cpasync16(unsigned int s, const void* g) {
    asm volatile("cp.async.cg.shared.global [%0], [%1], 16;" :: "r"(s), "l"(g));
}
#define CP_COMMIT() asm volatile("cp.async.commit_group;" ::: "memory")
#define CP_WAIT(n)  asm volatile("cp.async.wait_group %0;" :: "n"(n) : "memory")

// ---------------------------------------------------------------------------
// Projections: f32x2 accumulation over column pairs. Also: resets the attn
// work counter and writes 1.0 into V pad-dim 13 (Z-in-accumulator trick).
// ---------------------------------------------------------------------------
__global__ void __launch_bounds__(320) proj_kernel(PtrPack p) {
    int pid = blockIdx.y;
    const float* src = (pid < 4) ? p.x : (((pid & 1) == 0) ? p.y : p.z);
    const float* W = p.W[pid];
    float* dst = ((pid < 4) ? g_Q : (pid < 8 ? g_K : g_V)) + (pid & 3) * OPSTR;
    bool isQ = (pid < 4);

    __shared__ float Ws[78][80];
    __shared__ float in_s[64][80];
    int tid = threadIdx.x;
    int row0 = blockIdx.x * 64;

    if (pid == 0 && blockIdx.x == 0 && tid == 0) g_ctr = NBLK;

    // V pad-dim 13 := 1.0 for all 6 heads of this block's 64 rows
    if (pid >= 8 && tid < 64) {
        int rg = row0 + tid;
        int bb = rg >> 10, ii = rg & 1023;
        #pragma unroll
        for (int h = 0; h < 6; ++h)
            dst[(bb * 6 + h) * 16384 + (ii >> 1) * 32 + 26 + (ii & 1)] = 1.0f;
    }

    for (int idx = tid; idx < 78 * 80; idx += 320) {
        int k = idx / 80, c = idx % 80;
        Ws[k][c] = (c < 78) ? W[k * 78 + c] : 0.f;
    }
    for (int idx = tid; idx < 64 * 80; idx += 320) {
        int r = idx / 80, k = idx % 80;
        in_s[r][k] = (k < 78) ? src[(row0 + r) * 78 + k] : 0.f;
    }
    __syncthreads();

    int r0 = (tid / 20) * 4;
    int c0 = (tid % 20) * 4;
    ull acc2[4][2] = {};
    #pragma unroll 2
    for (int k = 0; k < 78; ++k) {
        float4 w = *(const float4*)&Ws[k][c0];
        ull w01 = pk(w.x, w.y), w23 = pk(w.z, w.w);
        #pragma unroll
        for (int i = 0; i < 4; ++i) {
            float a = in_s[r0 + i][k];
            ull aa = pk(a, a);
            acc2[i][0] = fma2(aa, w01, acc2[i][0]);
            acc2[i][1] = fma2(aa, w23, acc2[i][1]);
        }
    }
    #pragma unroll
    for (int i = 0; i < 4; ++i) {
        float av[4];
        upk(acc2[i][0], av[0], av[1]);
        upk(acc2[i][1], av[2], av[3]);
        int rg = row0 + r0 + i;
        int bb = rg >> 10, ii = rg & 1023;
        #pragma unroll
        for (int j = 0; j < 4; ++j) {
            int c = c0 + j;
            if (c < 78) {
                int h = c / 13, dd = c % 13;
                int base = (bb * 6 + h) * 16384;
                int off = isQ ? (ii * 16 + dd)
                              : ((ii >> 1) * 32 + dd * 2 + (ii & 1));
                dst[base + off] = av[j];
            }
        }
    }
}

// ---------------------------------------------------------------------------
// Persistent attention: 152 blocks x 256 threads pull 384 units
// (op,b,h,half). Thread = 2 queries; iteration = 2 keys; cp.async double
// buffering; 13-dim trimmed dot; Z folded into acc dim 13 (V pad = 1).
// ---------------------------------------------------------------------------
__device__ __forceinline__ void stage_tile(const float* g, float* s, int tid) {
    unsigned int sa = (unsigned int)__cvta_generic_to_shared(s);
    cpasync16(sa + tid * 16,            g + tid * 4);
    cpasync16(sa + (tid + 256) * 16,    g + (tid + 256) * 4);
}

// dot of both queries against a key pair; returns packed exponent args
__device__ __forceinline__ void dot2(const ull qd0[13], const ull qd1[13],
                                     const float* Krow,
                                     float& s0a, float& s0b, float& s1a, float& s1b,
                                     ull init0, ull init1) {
    const ulonglong2* kr = (const ulonglong2*)Krow;
    ull c00 = init0, c01 = 0, c10 = init1, c11 = 0;
    #pragma unroll
    for (int p = 0; p < 6; ++p) {
        ulonglong2 kk = kr[p];
        c00 = fma2(qd0[2*p],     kk.x, c00);
        c01 = fma2(qd0[2*p + 1], kk.y, c01);
        c10 = fma2(qd1[2*p],     kk.x, c10);
        c11 = fma2(qd1[2*p + 1], kk.y, c11);
    }
    ulonglong2 kk6 = kr[6];
    c00 = fma2(qd0[12], kk6.x, c00);
    c10 = fma2(qd1[12], kk6.x, c10);
    upk(add2(c00, c01), s0a, s0b);
    upk(add2(c10, c11), s1a, s1b);
}

__device__ __forceinline__ void pv(const float* Vrow, ull e0, ull e1,
                                   ull acc0[14], ull acc1[14]) {
    const ulonglong2* vr = (const ulonglong2*)Vrow;
    #pragma unroll
    for (int p = 0; p < 7; ++p) {
        ulonglong2 vv = vr[p];
        acc0[2*p]     = fma2(e0, vv.x, acc0[2*p]);
        acc0[2*p + 1] = fma2(e0, vv.y, acc0[2*p + 1]);
        acc1[2*p]     = fma2(e1, vv.x, acc1[2*p]);
        acc1[2*p + 1] = fma2(e1, vv.y, acc1[2*p + 1]);
    }
}

__global__ void __launch_bounds__(256) attn_kernel(float* __restrict__ out) {
    __shared__ float Kb[2][TKEYS * 16];
    __shared__ float Vb[2][TKEYS * 16];
    __shared__ int s_next;
    int tid = threadIdx.x;
    int u = blockIdx.x;

    while (u < NUNITS) {
        int half = u & 1;
        int rest = u >> 1;          // 0..191
        int h = rest % 6;
        int ob = rest / 6;          // 0..31
        int b = ob & 7, op = ob >> 3;

        int base = ((op * 8 + b) * 6 + h) * 16384;
        const float* Q = g_Q + base;
        const float* K = g_K + base;
        const float* V = g_V + base;
        int i0 = (half * 256 + tid) * 2;

        // load + pre-scale the two query rows (dims 0..12)
        ull qd0[13], qd1[13];
        {
            const float4* qa = (const float4*)&Q[i0 * 16];
            const float4* qb = (const float4*)&Q[(i0 + 1) * 16];
            #pragma unroll
            for (int p = 0; p < 4; ++p) {
                float4 a = qa[p], c = qb[p];
                #pragma unroll
                for (int e = 0; e < 4; ++e) {
                    int d = 4 * p + e;
                    if (d < 13) {
                        float va = (&a.x)[e] * CQ, vc = (&c.x)[e] * CQ;
                        qd0[d] = pk(va, va);
                        qd1[d] = pk(vc, vc);
                    }
                }
            }
        }

        int rowoff = (op == 0) ? 0 : (op == 1 ? 2048 : (op == 2 ? 1024 : 3072));
        float* o0 = out + ((size_t)b * OUT_ROWS + rowoff + i0) * 78 + h * 13;
        float* o1 = o0 + 78;

        if (op < 2) {
            // ------------- cross attention, single pass -------------
            ull acc0[14], acc1[14];
            #pragma unroll
            for (int d = 0; d < 14; ++d) { acc0[d] = 0; acc1[d] = 0; }

            stage_tile(K, Kb[0], tid);
            stage_tile(V, Vb[0], tid);
            CP_COMMIT();
            for (int t = 0; t < 8; ++t) {
                if (t < 7) {
                    stage_tile(K + (t + 1) * 2048, Kb[(t + 1) & 1], tid);
                    stage_tile(V + (t + 1) * 2048, Vb[(t + 1) & 1], tid);
                    CP_COMMIT();
                    CP_WAIT(1);
                } else {
                    CP_WAIT(0);
                }
                __syncthreads();
                const float* Kt = Kb[t & 1];
                const float* Vt = Vb[t & 1];
                #pragma unroll 2
                for (int j = 0; j < TKEYS / 2; ++j) {
                    float s0a, s0b, s1a, s1b;
                    dot2(qd0, qd1, Kt + j * 32, s0a, s0b, s1a, s1b, 0, 0);
                    ull e0 = pk(ex2(s0a), ex2(s0b));
                    ull e1 = pk(ex2(s1a), ex2(s1b));
                    pv(Vt + j * 32, e0, e1, acc0, acc1);
                }
                __syncthreads();
            }
            float za, zb;
            upk(acc0[13], za, zb); float iz0 = 1.f / (za + zb);
            upk(acc1[13], za, zb); float iz1 = 1.f / (za + zb);
            #pragma unroll
            for (int d = 0; d < 13; ++d) {
                float aa, ab;
                upk(acc0[d], aa, ab); o0[d] = (aa + ab) * iz0;
                upk(acc1[d], aa, ab); o1[d] = (aa + ab) * iz1;
            }
        } else {
            // ------------- contrastive pass 1: Z only -------------
            ull Zp0 = 0, Zp1 = 0;
            stage_tile(K, Kb[0], tid);
            CP_COMMIT();
            for (int t = 0; t < 8; ++t) {
                if (t < 7) {
                    stage_tile(K + (t + 1) * 2048, Kb[(t + 1) & 1], tid);
                    CP_COMMIT();
                    CP_WAIT(1);
                } else {
                    CP_WAIT(0);
                }
                __syncthreads();
                const float* Kt = Kb[t & 1];
                #pragma unroll 2
                for (int j = 0; j < TKEYS / 2; ++j) {
                    float s0a, s0b, s1a, s1b;
                    dot2(qd0, qd1, Kt + j * 32, s0a, s0b, s1a, s1b, 0, 0);
                    Zp0 = add2(Zp0, pk(ex2(s0a), ex2(s0b)));
                    Zp1 = add2(Zp1, pk(ex2(s1a), ex2(s1b)));
                }
                __syncthreads();
            }
            float za, zb;
            upk(Zp0, za, zb); float il0 = -lg2(za + zb);
            upk(Zp1, za, zb); float il1 = -lg2(za + zb);
            ull init0 = pk(il0, il0), init1 = pk(il1, il1);

            // ------------- pass 2: w = exp(-p), weighted V -------------
            ull acc0[14], acc1[14];
            #pragma unroll
            for (int d = 0; d < 14; ++d) { acc0[d] = 0; acc1[d] = 0; }

            stage_tile(K, Kb[0], tid);
            stage_tile(V, Vb[0], tid);
            CP_COMMIT();
            for (int t = 0; t < 8; ++t) {
                if (t < 7) {
                    stage_tile(K + (t + 1) * 2048, Kb[(t + 1) & 1], tid);
                    stage_tile(V + (t + 1) * 2048, Vb[(t + 1) & 1], tid);
                    CP_COMMIT();
                    CP_WAIT(1);
                } else {
                    CP_WAIT(0);
                }
                __syncthreads();
                const float* Kt = Kb[t & 1];
                const float* Vt = Vb[t & 1];
                #pragma unroll 2
                for (int j = 0; j < TKEYS / 2; ++j) {
                    float s0a, s0b, s1a, s1b;
                    dot2(qd0, qd1, Kt + j * 32, s0a, s0b, s1a, s1b, init0, init1);
                    ull e0 = pk(ex2(ex2(s0a) * NL2E), ex2(ex2(s0b) * NL2E));
                    ull e1 = pk(ex2(ex2(s1a) * NL2E), ex2(ex2(s1b) * NL2E));
                    pv(Vt + j * 32, e0, e1, acc0, acc1);
                }
                __syncthreads();
            }
            float ta, tb;
            upk(acc0[13], ta, tb); float it0 = 1.f / (ta + tb);
            upk(acc1[13], ta, tb); float it1 = 1.f / (ta + tb);
            const float* qr0 = &Q[i0 * 16];
            const float* qr1 = &Q[(i0 + 1) * 16];
            #pragma unroll
            for (int d = 0; d < 13; ++d) {
                float aa, ab;
                upk(acc0[d], aa, ab); o0[d] = qr0[d] + (aa + ab) * it0;
                upk(acc1[d], aa, ab); o1[d] = qr1[d] + (aa + ab) * it1;
            }
        }

        if (tid == 0) s_next = atomicAdd(&g_ctr, 1);
        __syncthreads();
        u = s_next;
    }
}

// ---------------------------------------------------------------------------
// Pooled tokens: 8-way row split per (b, tok) + smem reduce.
// ---------------------------------------------------------------------------
__global__ void __launch_bounds__(640) mean_kernel(const float* __restrict__ x,
                                                   const float* __restrict__ out) {
    __shared__ float red[8][78];
    int b = blockIdx.x, tok = blockIdx.y, t = threadIdx.x;
    if (t < 624) {
        int g = t / 78, c = t % 78;
        float s = 0.f;
        if (tok == 0) {
            const float* p = x + (size_t)b * 1024 * 78 + c;
            for (int i = g; i < 1024; i += 8) s += p[(size_t)i * 78];
        } else {
            int r0 = (tok == 1) ? 0 : 2048;
            const float* p = out + ((size_t)b * OUT_ROWS + r0) * 78 + c;
            for (int i = g; i < 2048; i += 8) s += p[(size_t)i * 78];
        }
        red[g][c] = s;
    }
    __syncthreads();
    if (t < 78) {
        float tot = 0.f;
        #pragma unroll
        for (int g = 0; g < 8; ++g) tot += red[g][t];
        g_tok[(b * 3 + tok) * 78 + t] = tot * (1.f / 1024.f);
    }
}

// ---------------------------------------------------------------------------
// Tiny 3-token MHSA on pooled tokens -> output rows 4096..4098.
// ---------------------------------------------------------------------------
__global__ void __launch_bounds__(704) fused_kernel(const float* __restrict__ Wq,
                                                    const float* __restrict__ Wk,
                                                    const float* __restrict__ Wv,
                                                    float* __restrict__ out) {
    __shared__ float tok[3][78];
    __shared__ float qs[3][78], ks[3][78], vs[3][78];
    __shared__ float ps[6][3][3];
    int b = blockIdx.x, t = threadIdx.x;

    for (int idx = t; idx < 234; idx += 704) tok[idx / 78][idx % 78] = g_tok[b * 234 + idx];
    __syncthreads();

    if (t < 702) {
        int comp = t / 234, rem = t % 234, i = rem / 78, c = rem % 78;
        const float* W = (comp == 0) ? Wq : ((comp == 1) ? Wk : Wv);
        float a = 0.f;
        #pragma unroll 13
        for (int k = 0; k < 78; ++k) a = fmaf(tok[i][k], __ldg(&W[k * 78 + c]), a);
        float (*dst)[78] = (comp == 0) ? qs : ((comp == 1) ? ks : vs);
        dst[i][c] = a;
    }
    __syncthreads();

    if (t < 54) {
        int h = t / 9, rem = t % 9, i = rem / 3, j = rem % 3;
        float s = 0.f;
        #pragma unroll
        for (int d = 0; d < 13; ++d) s = fmaf(qs[i][h * 13 + d], ks[j][h * 13 + d], s);
        ps[h][i][j] = s * SCALE;
    }
    __syncthreads();

    if (t < 18) {
        int h = t / 3, i = t % 3;
        float a = ps[h][i][0], bb = ps[h][i][1], c = ps[h][i][2];
        float mx = fmaxf(a, fmaxf(bb, c));
        float ea = ex2((a - mx) * L2E), eb = ex2((bb - mx) * L2E), ec = ex2((c - mx) * L2E);
        float inv = 1.f / (ea + eb + ec);
        ps[h][i][0] = ea * inv; ps[h][i][1] = eb * inv; ps[h][i][2] = ec * inv;
    }
    __syncthreads();

    if (t < 78) {
        int h = t / 13;
        #pragma unroll
        for (int i = 0; i < 3; ++i) {
            float o = ps[h][i][0] * vs[0][t] + ps[h][i][1] * vs[1][t] + ps[h][i][2] * vs[2][t];
            out[((size_t)b * OUT_ROWS + 4096 + i) * 78 + t] = o;
        }
    }
}

// ---------------------------------------------------------------------------
extern "C" void kernel_launch(void* const* d_in, const int* in_sizes, int n_in,
                              void* d_out, int out_size) {
    PtrPack p;
    p.x = (const float*)d_in[0];
    p.y = (const float*)d_in[1];
    p.z = (const float*)d_in[2];
    const int widx[12] = {5, 8, 11, 14,   // Q: tv, ta, ctv, cta
                          6, 9, 12, 15,   // K
                          7, 10, 13, 16}; // V
    for (int i = 0; i < 12; ++i) p.W[i] = (const float*)d_in[widx[i]];
    float* out = (float*)d_out;

    proj_kernel<<<dim3(128, 12), 320>>>(p);
    attn_kernel<<<NBLK, 256>>>(out);
    mean_kernel<<<dim3(8, 3), 640>>>((const float*)d_in[0], out);
    fused_kernel<<<8, 704>>>((const float*)d_in[17], (const float*)d_in[18],
                             (const float*)d_in[19], out);
}

// round 9
// speedup vs baseline: 1.6824x; 1.6824x over previous
#include <cuda_runtime.h>
#include <cstdint>

typedef unsigned long long ull;

#define OUT_ROWS 4099
#define OPSTR (8*6*1024*16)
#define SCALE 0.2773500981126146f
#define L2E   1.4426950408889634f
#define NL2E  (-1.4426950408889634f)
#define CQ    (SCALE*L2E)
#define TKEYS 128
#define NUNITS 384
#define NBLK 304

// scratch (device globals; no allocations allowed)
__device__ float g_Q[4*OPSTR];   // [op][b][h][i][16]
__device__ float g_K[4*OPSTR];   // [op][b][h][pair][dim][2]  pair-interleaved
__device__ float g_V[4*OPSTR];   // same layout; dim13 lane := 1.0 (Z trick)
__device__ float g_tok[8*3*78];
__device__ int   g_ctr;

struct PtrPack {
    const float* x; const float* y; const float* z;
    const float* W[12];   // 0..3 Q(tv,ta,ctv,cta), 4..7 K, 8..11 V
};

__device__ __forceinline__ float ex2(float v) {
    float r; asm("ex2.approx.ftz.f32 %0, %1;" : "=f"(r) : "f"(v)); return r;
}
__device__ __forceinline__ float lg2(float v) {
    float r; asm("lg2.approx.ftz.f32 %0, %1;" : "=f"(r) : "f"(v)); return r;
}
__device__ __forceinline__ ull pk(float lo, float hi) {
    ull r; asm("mov.b64 %0, {%1,%2};" : "=l"(r) : "f"(lo), "f"(hi)); return r;
}
__device__ __forceinline__ void upk(ull v, float& lo, float& hi) {
    asm("mov.b64 {%0,%1}, %2;" : "=f"(lo), "=f"(hi) : "l"(v));
}
__device__ __forceinline__ ull fma2(ull a, ull b, ull c) {
    ull d; asm("fma.rn.f32x2 %0, %1, %2, %3;" : "=l"(d) : "l"(a), "l"(b), "l"(c)); return d;
}
__device__ __forceinline__ ull add2(ull a, ull b) {
    ull d; asm("add.rn.f32x2 %0, %1, %2;" : "=l"(d) : "l"(a), "l"(b)); return d;
}
__device__ __forceinline__ void cpasync16(unsigned int s, const void* g) {
    asm volatile("cp.async.cg.shared.global [%0], [%1], 16;" :: "r"(s), "l"(g));
}
#define CP_COMMIT() asm volatile("cp.async.commit_group;" ::: "memory")
#define CP_WAIT(n)  asm volatile("cp.async.wait_group %0;" :: "n"(n) : "memory")

// ---------------------------------------------------------------------------
// Projections: f32x2 accumulation over column pairs. Also: resets the attn
// work counter and writes 1.0 into V pad-dim 13 (Z-in-accumulator trick).
// ---------------------------------------------------------------------------
__global__ void __launch_bounds__(320) proj_kernel(PtrPack p) {
    int pid = blockIdx.y;
    const float* src = (pid < 4) ? p.x : (((pid & 1) == 0) ? p.y : p.z);
    const float* W = p.W[pid];
    float* dst = ((pid < 4) ? g_Q : (pid < 8 ? g_K : g_V)) + (pid & 3) * OPSTR;
    bool isQ = (pid < 4);

    __shared__ float Ws[78][80];
    __shared__ float in_s[64][80];
    int tid = threadIdx.x;
    int row0 = blockIdx.x * 64;

    if (pid == 0 && blockIdx.x == 0 && tid == 0) g_ctr = NBLK;

    // V pad-dim 13 := 1.0 for all 6 heads of this block's 64 rows
    if (pid >= 8 && tid < 64) {
        int rg = row0 + tid;
        int bb = rg >> 10, ii = rg & 1023;
        #pragma unroll
        for (int h = 0; h < 6; ++h)
            dst[(bb * 6 + h) * 16384 + (ii >> 1) * 32 + 26 + (ii & 1)] = 1.0f;
    }

    for (int idx = tid; idx < 78 * 80; idx += 320) {
        int k = idx / 80, c = idx % 80;
        Ws[k][c] = (c < 78) ? W[k * 78 + c] : 0.f;
    }
    for (int idx = tid; idx < 64 * 80; idx += 320) {
        int r = idx / 80, k = idx % 80;
        in_s[r][k] = (k < 78) ? src[(row0 + r) * 78 + k] : 0.f;
    }
    __syncthreads();

    int r0 = (tid / 20) * 4;
    int c0 = (tid % 20) * 4;
    ull acc2[4][2] = {};
    #pragma unroll 2
    for (int k = 0; k < 78; ++k) {
        float4 w = *(const float4*)&Ws[k][c0];
        ull w01 = pk(w.x, w.y), w23 = pk(w.z, w.w);
        #pragma unroll
        for (int i = 0; i < 4; ++i) {
            float a = in_s[r0 + i][k];
            ull aa = pk(a, a);
            acc2[i][0] = fma2(aa, w01, acc2[i][0]);
            acc2[i][1] = fma2(aa, w23, acc2[i][1]);
        }
    }
    #pragma unroll
    for (int i = 0; i < 4; ++i) {
        float av[4];
        upk(acc2[i][0], av[0], av[1]);
        upk(acc2[i][1], av[2], av[3]);
        int rg = row0 + r0 + i;
        int bb = rg >> 10, ii = rg & 1023;
        #pragma unroll
        for (int j = 0; j < 4; ++j) {
            int c = c0 + j;
            if (c < 78) {
                int h = c / 13, dd = c % 13;
                int base = (bb * 6 + h) * 16384;
                int off = isQ ? (ii * 16 + dd)
                              : ((ii >> 1) * 32 + dd * 2 + (ii & 1));
                dst[base + off] = av[j];
            }
        }
    }
}

// ---------------------------------------------------------------------------
// Persistent attention: 304 blocks (2 CTAs/SM) x 256 threads pull 384 units
// (op,b,h,half). Thread = 2 queries; iteration = 2 keys; cp.async double
// buffering; 13-dim trimmed dot; Z folded into acc dim 13 (V pad = 1).
// ---------------------------------------------------------------------------
__device__ __forceinline__ void stage_tile(const float* g, float* s, int tid) {
    unsigned int sa = (unsigned int)__cvta_generic_to_shared(s);
    cpasync16(sa + tid * 16,            g + tid * 4);
    cpasync16(sa + (tid + 256) * 16,    g + (tid + 256) * 4);
}

// dot of both queries against a key pair
__device__ __forceinline__ void dot2(const ull qd0[13], const ull qd1[13],
                                     const float* Krow,
                                     float& s0a, float& s0b, float& s1a, float& s1b,
                                     ull init0, ull init1) {
    const ulonglong2* kr = (const ulonglong2*)Krow;
    ull c00 = init0, c01 = 0, c10 = init1, c11 = 0;
    #pragma unroll
    for (int p = 0; p < 6; ++p) {
        ulonglong2 kk = kr[p];
        c00 = fma2(qd0[2*p],     kk.x, c00);
        c01 = fma2(qd0[2*p + 1], kk.y, c01);
        c10 = fma2(qd1[2*p],     kk.x, c10);
        c11 = fma2(qd1[2*p + 1], kk.y, c11);
    }
    ulonglong2 kk6 = kr[6];
    c00 = fma2(qd0[12], kk6.x, c00);
    c10 = fma2(qd1[12], kk6.x, c10);
    upk(add2(c00, c01), s0a, s0b);
    upk(add2(c10, c11), s1a, s1b);
}

__device__ __forceinline__ void pv(const float* Vrow, ull e0, ull e1,
                                   ull acc0[14], ull acc1[14]) {
    const ulonglong2* vr = (const ulonglong2*)Vrow;
    #pragma unroll
    for (int p = 0; p < 7; ++p) {
        ulonglong2 vv = vr[p];
        acc0[2*p]     = fma2(e0, vv.x, acc0[2*p]);
        acc0[2*p + 1] = fma2(e0, vv.y, acc0[2*p + 1]);
        acc1[2*p]     = fma2(e1, vv.x, acc1[2*p]);
        acc1[2*p + 1] = fma2(e1, vv.y, acc1[2*p + 1]);
    }
}

__global__ void __launch_bounds__(256, 2) attn_kernel(float* __restrict__ out) {
    __shared__ float Kb[2][TKEYS * 16];
    __shared__ float Vb[2][TKEYS * 16];
    __shared__ int s_next;
    int tid = threadIdx.x;
    int u = blockIdx.x;

    while (u < NUNITS) {
        int half = u & 1;
        int rest = u >> 1;          // 0..191
        int h = rest % 6;
        int ob = rest / 6;          // 0..31
        int b = ob & 7, op = ob >> 3;

        int base = ((op * 8 + b) * 6 + h) * 16384;
        const float* Q = g_Q + base;
        const float* K = g_K + base;
        const float* V = g_V + base;
        int i0 = (half * 256 + tid) * 2;

        // load + pre-scale the two query rows (dims 0..12)
        ull qd0[13], qd1[13];
        {
            const float4* qa = (const float4*)&Q[i0 * 16];
            const float4* qb = (const float4*)&Q[(i0 + 1) * 16];
            #pragma unroll
            for (int p = 0; p < 4; ++p) {
                float4 a = qa[p], c = qb[p];
                #pragma unroll
                for (int e = 0; e < 4; ++e) {
                    int d = 4 * p + e;
                    if (d < 13) {
                        float va = (&a.x)[e] * CQ, vc = (&c.x)[e] * CQ;
                        qd0[d] = pk(va, va);
                        qd1[d] = pk(vc, vc);
                    }
                }
            }
        }

        int rowoff = (op == 0) ? 0 : (op == 1 ? 2048 : (op == 2 ? 1024 : 3072));
        float* o0 = out + ((size_t)b * OUT_ROWS + rowoff + i0) * 78 + h * 13;
        float* o1 = o0 + 78;

        if (op < 2) {
            // ------------- cross attention, single pass -------------
            ull acc0[14], acc1[14];
            #pragma unroll
            for (int d = 0; d < 14; ++d) { acc0[d] = 0; acc1[d] = 0; }

            stage_tile(K, Kb[0], tid);
            stage_tile(V, Vb[0], tid);
            CP_COMMIT();
            for (int t = 0; t < 8; ++t) {
                if (t < 7) {
                    stage_tile(K + (t + 1) * 2048, Kb[(t + 1) & 1], tid);
                    stage_tile(V + (t + 1) * 2048, Vb[(t + 1) & 1], tid);
                    CP_COMMIT();
                    CP_WAIT(1);
                } else {
                    CP_WAIT(0);
                }
                __syncthreads();
                const float* Kt = Kb[t & 1];
                const float* Vt = Vb[t & 1];
                #pragma unroll 2
                for (int j = 0; j < TKEYS / 2; ++j) {
                    float s0a, s0b, s1a, s1b;
                    dot2(qd0, qd1, Kt + j * 32, s0a, s0b, s1a, s1b, 0, 0);
                    ull e0 = pk(ex2(s0a), ex2(s0b));
                    ull e1 = pk(ex2(s1a), ex2(s1b));
                    pv(Vt + j * 32, e0, e1, acc0, acc1);
                }
                __syncthreads();
            }
            float za, zb;
            upk(acc0[13], za, zb); float iz0 = 1.f / (za + zb);
            upk(acc1[13], za, zb); float iz1 = 1.f / (za + zb);
            #pragma unroll
            for (int d = 0; d < 13; ++d) {
                float aa, ab;
                upk(acc0[d], aa, ab); o0[d] = (aa + ab) * iz0;
                upk(acc1[d], aa, ab); o1[d] = (aa + ab) * iz1;
            }
        } else {
            // ------------- contrastive pass 1: Z only -------------
            ull Zp0 = 0, Zp1 = 0;
            stage_tile(K, Kb[0], tid);
            CP_COMMIT();
            for (int t = 0; t < 8; ++t) {
                if (t < 7) {
                    stage_tile(K + (t + 1) * 2048, Kb[(t + 1) & 1], tid);
                    CP_COMMIT();
                    CP_WAIT(1);
                } else {
                    CP_WAIT(0);
                }
                __syncthreads();
                const float* Kt = Kb[t & 1];
                #pragma unroll 2
                for (int j = 0; j < TKEYS / 2; ++j) {
                    float s0a, s0b, s1a, s1b;
                    dot2(qd0, qd1, Kt + j * 32, s0a, s0b, s1a, s1b, 0, 0);
                    Zp0 = add2(Zp0, pk(ex2(s0a), ex2(s0b)));
                    Zp1 = add2(Zp1, pk(ex2(s1a), ex2(s1b)));
                }
                __syncthreads();
            }
            float za, zb;
            upk(Zp0, za, zb); float il0 = -lg2(za + zb);
            upk(Zp1, za, zb); float il1 = -lg2(za + zb);
            ull init0 = pk(il0, il0), init1 = pk(il1, il1);

            // ------------- pass 2: w = exp(-p), weighted V -------------
            ull acc0[14], acc1[14];
            #pragma unroll
            for (int d = 0; d < 14; ++d) { acc0[d] = 0; acc1[d] = 0; }

            stage_tile(K, Kb[0], tid);
            stage_tile(V, Vb[0], tid);
            CP_COMMIT();
            for (int t = 0; t < 8; ++t) {
                if (t < 7) {
                    stage_tile(K + (t + 1) * 2048, Kb[(t + 1) & 1], tid);
                    stage_tile(V + (t + 1) * 2048, Vb[(t + 1) & 1], tid);
                    CP_COMMIT();
                    CP_WAIT(1);
                } else {
                    CP_WAIT(0);
                }
                __syncthreads();
                const float* Kt = Kb[t & 1];
                const float* Vt = Vb[t & 1];
                #pragma unroll 2
                for (int j = 0; j < TKEYS / 2; ++j) {
                    float s0a, s0b, s1a, s1b;
                    dot2(qd0, qd1, Kt + j * 32, s0a, s0b, s1a, s1b, init0, init1);
                    ull e0 = pk(ex2(ex2(s0a) * NL2E), ex2(ex2(s0b) * NL2E));
                    ull e1 = pk(ex2(ex2(s1a) * NL2E), ex2(ex2(s1b) * NL2E));
                    pv(Vt + j * 32, e0, e1, acc0, acc1);
                }
                __syncthreads();
            }
            float ta, tb;
            upk(acc0[13], ta, tb); float it0 = 1.f / (ta + tb);
            upk(acc1[13], ta, tb); float it1 = 1.f / (ta + tb);
            const float* qr0 = &Q[i0 * 16];
            const float* qr1 = &Q[(i0 + 1) * 16];
            #pragma unroll
            for (int d = 0; d < 13; ++d) {
                float aa, ab;
                upk(acc0[d], aa, ab); o0[d] = qr0[d] + (aa + ab) * it0;
                upk(acc1[d], aa, ab); o1[d] = qr1[d] + (aa + ab) * it1;
            }
        }

        if (tid == 0) s_next = atomicAdd(&g_ctr, 1);
        __syncthreads();
        u = s_next;
    }
}

// ---------------------------------------------------------------------------
// Pooled tokens: 8-way row split per (b, tok) + smem reduce.
// ---------------------------------------------------------------------------
__global__ void __launch_bounds__(640) mean_kernel(const float* __restrict__ x,
                                                   const float* __restrict__ out) {
    __shared__ float red[8][78];
    int b = blockIdx.x, tok = blockIdx.y, t = threadIdx.x;
    if (t < 624) {
        int g = t / 78, c = t % 78;
        float s = 0.f;
        if (tok == 0) {
            const float* p = x + (size_t)b * 1024 * 78 + c;
            for (int i = g; i < 1024; i += 8) s += p[(size_t)i * 78];
        } else {
            int r0 = (tok == 1) ? 0 : 2048;
            const float* p = out + ((size_t)b * OUT_ROWS + r0) * 78 + c;
            for (int i = g; i < 2048; i += 8) s += p[(size_t)i * 78];
        }
        red[g][c] = s;
    }
    __syncthreads();
    if (t < 78) {
        float tot = 0.f;
        #pragma unroll
        for (int g = 0; g < 8; ++g) tot += red[g][t];
        g_tok[(b * 3 + tok) * 78 + t] = tot * (1.f / 1024.f);
    }
}

// ---------------------------------------------------------------------------
// Tiny 3-token MHSA on pooled tokens -> output rows 4096..4098.
// ---------------------------------------------------------------------------
__global__ void __launch_bounds__(704) fused_kernel(const float* __restrict__ Wq,
                                                    const float* __restrict__ Wk,
                                                    const float* __restrict__ Wv,
                                                    float* __restrict__ out) {
    __shared__ float tok[3][78];
    __shared__ float qs[3][78], ks[3][78], vs[3][78];
    __shared__ float ps[6][3][3];
    int b = blockIdx.x, t = threadIdx.x;

    for (int idx = t; idx < 234; idx += 704) tok[idx / 78][idx % 78] = g_tok[b * 234 + idx];
    __syncthreads();

    if (t < 702) {
        int comp = t / 234, rem = t % 234, i = rem / 78, c = rem % 78;
        const float* W = (comp == 0) ? Wq : ((comp == 1) ? Wk : Wv);
        float a = 0.f;
        #pragma unroll 13
        for (int k = 0; k < 78; ++k) a = fmaf(tok[i][k], __ldg(&W[k * 78 + c]), a);
        float (*dst)[78] = (comp == 0) ? qs : ((comp == 1) ? ks : vs);
        dst[i][c] = a;
    }
    __syncthreads();

    if (t < 54) {
        int h = t / 9, rem = t % 9, i = rem / 3, j = rem % 3;
        float s = 0.f;
        #pragma unroll
        for (int d = 0; d < 13; ++d) s = fmaf(qs[i][h * 13 + d], ks[j][h * 13 + d], s);
        ps[h][i][j] = s * SCALE;
    }
    __syncthreads();

    if (t < 18) {
        int h = t / 3, i = t % 3;
        float a = ps[h][i][0], bb = ps[h][i][1], c = ps[h][i][2];
        float mx = fmaxf(a, fmaxf(bb, c));
        float ea = ex2((a - mx) * L2E), eb = ex2((bb - mx) * L2E), ec = ex2((c - mx) * L2E);
        float inv = 1.f / (ea + eb + ec);
        ps[h][i][0] = ea * inv; ps[h][i][1] = eb * inv; ps[h][i][2] = ec * inv;
    }
    __syncthreads();

    if (t < 78) {
        int h = t / 13;
        #pragma unroll
        for (int i = 0; i < 3; ++i) {
            float o = ps[h][i][0] * vs[0][t] + ps[h][i][1] * vs[1][t] + ps[h][i][2] * vs[2][t];
            out[((size_t)b * OUT_ROWS + 4096 + i) * 78 + t] = o;
        }
    }
}

// ---------------------------------------------------------------------------
extern "C" void kernel_launch(void* const* d_in, const int* in_sizes, int n_in,
                              void* d_out, int out_size) {
    PtrPack p;
    p.x = (const float*)d_in[0];
    p.y = (const float*)d_in[1];
    p.z = (const float*)d_in[2];
    const int widx[12] = {5, 8, 11, 14,   // Q: tv, ta, ctv, cta
                          6, 9, 12, 15,   // K
                          7, 10, 13, 16}; // V
    for (int i = 0; i < 12; ++i) p.W[i] = (const float*)d_in[widx[i]];
    float* out = (float*)d_out;

    proj_kernel<<<dim3(128, 12), 320>>>(p);
    attn_kernel<<<NBLK, 256>>>(out);
    mean_kernel<<<dim3(8, 3), 640>>>((const float*)d_in[0], out);
    fused_kernel<<<8, 704>>>((const float*)d_in[17], (const float*)d_in[18],
                             (const float*)d_in[19], out);
}

// round 10
// speedup vs baseline: 4.2785x; 2.5430x over previous
#include <cuda_runtime.h>
#include <cuda_bf16.h>
#include <cstdint>

#define OUT_ROWS 4099
#define HSTR 16384                 // per-head element stride (1024*16)
#define SCALE 0.2773500981126146f
#define L2E   1.4426950408889634f
#define NL2E  (-1.4426950408889634f)
#define CQ    (SCALE*L2E)
#define NUNITS 768
#define NBLK 304
#define VSTR 136                   // Vt smem key-stride (bank-conflict-free)

// device scratch (zero-initialized; pad dims 13..15 never written)
__device__ float         g_Q [4*8*6*HSTR];   // fp32 [op][b][h][i][16]
__device__ __nv_bfloat16 g_Kb[4*8*6*HSTR];   // bf16 [op][b][h][key][16]
__device__ __nv_bfloat16 g_Vt[4*8*6*HSTR];   // bf16 [op][b][h][dim16][1024] (V^T)
__device__ float g_tok[8*3*78];
__device__ int   g_ctr;

struct PtrPack {
    const float* x; const float* y; const float* z;
    const float* W[12];
};

__device__ __forceinline__ float ex2(float v) {
    float r; asm("ex2.approx.ftz.f32 %0, %1;" : "=f"(r) : "f"(v)); return r;
}
__device__ __forceinline__ float lg2(float v) {
    float r; asm("lg2.approx.ftz.f32 %0, %1;" : "=f"(r) : "f"(v)); return r;
}
__device__ __forceinline__ uint32_t pbf(float lo, float hi) {   // pack 2 fp32 -> bf16x2 (lo = element0)
    uint32_t r; asm("cvt.rn.bf16x2.f32 %0, %1, %2;" : "=r"(r) : "f"(hi), "f"(lo)); return r;
}
__device__ __forceinline__ void mma_bf16(float d[4], const uint32_t a[4],
                                         uint32_t b0, uint32_t b1) {
    asm volatile("mma.sync.aligned.m16n8k16.row.col.f32.bf16.bf16.f32 "
                 "{%0,%1,%2,%3}, {%4,%5,%6,%7}, {%8,%9}, {%0,%1,%2,%3};"
                 : "+f"(d[0]), "+f"(d[1]), "+f"(d[2]), "+f"(d[3])
                 : "r"(a[0]), "r"(a[1]), "r"(a[2]), "r"(a[3]), "r"(b0), "r"(b1));
}
__device__ __forceinline__ float rsum4(float v) {
    v += __shfl_xor_sync(0xffffffffu, v, 1);
    v += __shfl_xor_sync(0xffffffffu, v, 2);
    return v;
}

// ---------------------------------------------------------------------------
// Projections -> g_Q (fp32 padded), g_Kb (bf16 row-major), g_Vt (bf16 V^T).
// Also resets the attention work counter.
// ---------------------------------------------------------------------------
__global__ void __launch_bounds__(320) proj_kernel(PtrPack p) {
    int pid = blockIdx.y;
    const float* src = (pid < 4) ? p.x : (((pid & 1) == 0) ? p.y : p.z);
    const float* W = p.W[pid];

    __shared__ float Ws[78][80];
    __shared__ float in_s[64][80];
    int tid = threadIdx.x;
    int row0 = blockIdx.x * 64;

    if (pid == 0 && blockIdx.x == 0 && tid == 0) g_ctr = NBLK;

    for (int idx = tid; idx < 78 * 80; idx += 320) {
        int k = idx / 80, c = idx % 80;
        Ws[k][c] = (c < 78) ? W[k * 78 + c] : 0.f;
    }
    for (int idx = tid; idx < 64 * 80; idx += 320) {
        int r = idx / 80, k = idx % 80;
        in_s[r][k] = (k < 78) ? src[(row0 + r) * 78 + k] : 0.f;
    }
    __syncthreads();

    int r0 = (tid / 20) * 4;
    int c0 = (tid % 20) * 4;
    float acc[4][4] = {};
    #pragma unroll 2
    for (int k = 0; k < 78; ++k) {
        float4 w = *(const float4*)&Ws[k][c0];
        #pragma unroll
        for (int i = 0; i < 4; ++i) {
            float a = in_s[r0 + i][k];
            acc[i][0] = fmaf(a, w.x, acc[i][0]);
            acc[i][1] = fmaf(a, w.y, acc[i][1]);
            acc[i][2] = fmaf(a, w.z, acc[i][2]);
            acc[i][3] = fmaf(a, w.w, acc[i][3]);
        }
    }
    int opi = pid & 3;
    #pragma unroll
    for (int i = 0; i < 4; ++i) {
        int rg = row0 + r0 + i;
        int bb = rg >> 10, ii = rg & 1023;
        #pragma unroll
        for (int j = 0; j < 4; ++j) {
            int c = c0 + j;
            if (c < 78) {
                int h = c / 13, dd = c % 13;
                int base = ((opi * 8 + bb) * 6 + h) * HSTR;
                if (pid < 4)       g_Q [base + ii * 16 + dd] = acc[i][j];
                else if (pid < 8)  g_Kb[base + ii * 16 + dd] = __float2bfloat16(acc[i][j]);
                else               g_Vt[base + dd * 1024 + ii] = __float2bfloat16(acc[i][j]);
            }
        }
    }
}

// ---------------------------------------------------------------------------
// Tensor-core attention. 768 units = (op,b,h,quarter). CTA = 256 thr = 8 warps,
// warp = 32 queries = 2 x m16 tiles; keys looped in 8 tiles of 128.
// QK and PV are mma.sync m16n8k16 bf16 with fp32 accum.
// ---------------------------------------------------------------------------
__global__ void __launch_bounds__(256, 2) attn_kernel(float* __restrict__ out) {
    __shared__ __nv_bfloat16 Kt[128 * 16];    // [key][dim]
    __shared__ __nv_bfloat16 Vt[16 * VSTR];   // [dim][key], padded
    __shared__ int s_next;
    int tid = threadIdx.x;
    int lane = tid & 31;
    int warp = tid >> 5;
    int lq = lane >> 2;          // row-in-tile 0..7
    int lc = lane & 3;           // col group 0..3
    int u = blockIdx.x;

    while (u < NUNITS) {
        int quarter = u & 3;
        int rest = u >> 2;             // 0..191
        int op = (rest / 48) ^ 2;      // contrastive units first
        int bh = rest % 48;
        int b = bh / 6, h = bh % 6;
        int base = ((op * 8 + b) * 6 + h) * HSTR;
        const float* Q = g_Q + base;
        const __nv_bfloat16* Kg = g_Kb + base;
        const __nv_bfloat16* Vg = g_Vt + base;
        int q0 = quarter * 256 + warp * 32;

        // ---- Q A-fragments (2 m16 tiles), CQ folded, bf16 ----
        uint32_t qa[2][4];
        #pragma unroll
        for (int m = 0; m < 2; ++m) {
            int row = q0 + m * 16 + lq;
            int col = 2 * lc;
            float2 v0 = *(const float2*)&Q[row * 16 + col];
            float2 v1 = *(const float2*)&Q[(row + 8) * 16 + col];
            float2 v2 = *(const float2*)&Q[row * 16 + col + 8];
            float2 v3 = *(const float2*)&Q[(row + 8) * 16 + col + 8];
            qa[m][0] = pbf(v0.x * CQ, v0.y * CQ);
            qa[m][1] = pbf(v1.x * CQ, v1.y * CQ);
            qa[m][2] = pbf(v2.x * CQ, v2.y * CQ);
            qa[m][3] = pbf(v3.x * CQ, v3.y * CQ);
        }

        int rowoff = (op == 0) ? 0 : (op == 1 ? 2048 : (op == 2 ? 1024 : 3072));

        if (op < 2) {
            // ================= cross attention, single pass =================
            float dacc[2][2][4] = {};
            float zz[2][2] = {};
            for (int t = 0; t < 8; ++t) {
                __syncthreads();
                ((uint4*)Kt)[tid] = ((const uint4*)(Kg + t * 2048))[tid];
                {
                    int r = tid >> 4, c = tid & 15;
                    uint4 v = *(const uint4*)(Vg + r * 1024 + t * 128 + c * 8);
                    *(uint4*)&Vt[r * VSTR + c * 8] = v;
                }
                __syncthreads();
                #pragma unroll 2
                for (int kc = 0; kc < 8; ++kc) {
                    int n0 = kc * 16;
                    float sD[2][2][4] = {};
                    #pragma unroll
                    for (int hf = 0; hf < 2; ++hf) {
                        int nn = n0 + hf * 8;
                        uint32_t b0 = *(const uint32_t*)&Kt[(nn + lq) * 16 + 2 * lc];
                        uint32_t b1 = *(const uint32_t*)&Kt[(nn + lq) * 16 + 2 * lc + 8];
                        mma_bf16(sD[0][hf], qa[0], b0, b1);
                        mma_bf16(sD[1][hf], qa[1], b0, b1);
                    }
                    uint32_t pa[2][4];
                    #pragma unroll
                    for (int m = 0; m < 2; ++m) {
                        #pragma unroll
                        for (int hf = 0; hf < 2; ++hf) {
                            float e0 = ex2(sD[m][hf][0]);
                            float e1 = ex2(sD[m][hf][1]);
                            float e2 = ex2(sD[m][hf][2]);
                            float e3 = ex2(sD[m][hf][3]);
                            zz[m][0] += e0 + e1;
                            zz[m][1] += e2 + e3;
                            pa[m][hf * 2]     = pbf(e0, e1);
                            pa[m][hf * 2 + 1] = pbf(e2, e3);
                        }
                    }
                    // NOTE: a-frag order must be {a0,a1,a2,a3} = {(r,k0-1),(r+8,k0-1),(r,k8-15),(r+8,k8-15)}
                    uint32_t af0[4] = {pa[0][0], pa[0][1], pa[0][2], pa[0][3]};
                    uint32_t af1[4] = {pa[1][0], pa[1][1], pa[1][2], pa[1][3]};
                    #pragma unroll
                    for (int nd = 0; nd < 2; ++nd) {
                        uint32_t vb0 = *(const uint32_t*)&Vt[(nd * 8 + lq) * VSTR + n0 + 2 * lc];
                        uint32_t vb1 = *(const uint32_t*)&Vt[(nd * 8 + lq) * VSTR + n0 + 2 * lc + 8];
                        mma_bf16(dacc[0][nd], af0, vb0, vb1);
                        mma_bf16(dacc[1][nd], af1, vb0, vb1);
                    }
                }
            }
            #pragma unroll
            for (int m = 0; m < 2; ++m) {
                float izA = 1.f / rsum4(zz[m][0]);
                float izB = 1.f / rsum4(zz[m][1]);
                int row = rowoff + q0 + m * 16 + lq;
                float* o1 = out + ((size_t)b * OUT_ROWS + row) * 78 + h * 13;
                float* o2 = o1 + (size_t)8 * 78;
                #pragma unroll
                for (int nd = 0; nd < 2; ++nd) {
                    int d = nd * 8 + 2 * lc;
                    if (d < 13)     o1[d]     = dacc[m][nd][0] * izA;
                    if (d + 1 < 13) o1[d + 1] = dacc[m][nd][1] * izA;
                    if (d < 13)     o2[d]     = dacc[m][nd][2] * izB;
                    if (d + 1 < 13) o2[d + 1] = dacc[m][nd][3] * izB;
                }
            }
        } else {
            // ================= contrastive: pass 1 (Z) =================
            float zz[2][2] = {};
            for (int t = 0; t < 8; ++t) {
                __syncthreads();
                ((uint4*)Kt)[tid] = ((const uint4*)(Kg + t * 2048))[tid];
                __syncthreads();
                #pragma unroll 2
                for (int kc = 0; kc < 8; ++kc) {
                    int n0 = kc * 16;
                    #pragma unroll
                    for (int hf = 0; hf < 2; ++hf) {
                        int nn = n0 + hf * 8;
                        uint32_t b0 = *(const uint32_t*)&Kt[(nn + lq) * 16 + 2 * lc];
                        uint32_t b1 = *(const uint32_t*)&Kt[(nn + lq) * 16 + 2 * lc + 8];
                        float sD[2][4] = {};
                        mma_bf16(sD[0], qa[0], b0, b1);
                        mma_bf16(sD[1], qa[1], b0, b1);
                        #pragma unroll
                        for (int m = 0; m < 2; ++m) {
                            zz[m][0] += ex2(sD[m][0]) + ex2(sD[m][1]);
                            zz[m][1] += ex2(sD[m][2]) + ex2(sD[m][3]);
                        }
                    }
                }
            }
            float il[2][2];
            #pragma unroll
            for (int m = 0; m < 2; ++m) {
                il[m][0] = -lg2(rsum4(zz[m][0]));
                il[m][1] = -lg2(rsum4(zz[m][1]));
            }
            // ============ pass 2: p = 2^(s - log2 Z); w = exp(-p) ============
            float dacc[2][2][4] = {};
            float tt[2][2] = {};
            for (int t = 0; t < 8; ++t) {
                __syncthreads();
                ((uint4*)Kt)[tid] = ((const uint4*)(Kg + t * 2048))[tid];
                {
                    int r = tid >> 4, c = tid & 15;
                    uint4 v = *(const uint4*)(Vg + r * 1024 + t * 128 + c * 8);
                    *(uint4*)&Vt[r * VSTR + c * 8] = v;
                }
                __syncthreads();
                #pragma unroll 2
                for (int kc = 0; kc < 8; ++kc) {
                    int n0 = kc * 16;
                    float sD[2][2][4];
                    #pragma unroll
                    for (int hf = 0; hf < 2; ++hf) {
                        int nn = n0 + hf * 8;
                        uint32_t b0 = *(const uint32_t*)&Kt[(nn + lq) * 16 + 2 * lc];
                        uint32_t b1 = *(const uint32_t*)&Kt[(nn + lq) * 16 + 2 * lc + 8];
                        #pragma unroll
                        for (int m = 0; m < 2; ++m) {
                            sD[m][hf][0] = il[m][0]; sD[m][hf][1] = il[m][0];
                            sD[m][hf][2] = il[m][1]; sD[m][hf][3] = il[m][1];
                            mma_bf16(sD[m][hf], qa[m], b0, b1);
                        }
                    }
                    uint32_t pa[2][4];
                    #pragma unroll
                    for (int m = 0; m < 2; ++m) {
                        #pragma unroll
                        for (int hf = 0; hf < 2; ++hf) {
                            float w0 = ex2(ex2(sD[m][hf][0]) * NL2E);
                            float w1 = ex2(ex2(sD[m][hf][1]) * NL2E);
                            float w2 = ex2(ex2(sD[m][hf][2]) * NL2E);
                            float w3 = ex2(ex2(sD[m][hf][3]) * NL2E);
                            tt[m][0] += w0 + w1;
                            tt[m][1] += w2 + w3;
                            pa[m][hf * 2]     = pbf(w0, w1);
                            pa[m][hf * 2 + 1] = pbf(w2, w3);
                        }
                    }
                    #pragma unroll
                    for (int nd = 0; nd < 2; ++nd) {
                        uint32_t vb0 = *(const uint32_t*)&Vt[(nd * 8 + lq) * VSTR + n0 + 2 * lc];
                        uint32_t vb1 = *(const uint32_t*)&Vt[(nd * 8 + lq) * VSTR + n0 + 2 * lc + 8];
                        mma_bf16(dacc[0][nd], pa[0], vb0, vb1);
                        mma_bf16(dacc[1][nd], pa[1], vb0, vb1);
                    }
                }
            }
            #pragma unroll
            for (int m = 0; m < 2; ++m) {
                float iTA = 1.f / rsum4(tt[m][0]);
                float iTB = 1.f / rsum4(tt[m][1]);
                int qrow = q0 + m * 16 + lq;
                int row = rowoff + qrow;
                float* o1 = out + ((size_t)b * OUT_ROWS + row) * 78 + h * 13;
                float* o2 = o1 + (size_t)8 * 78;
                #pragma unroll
                for (int nd = 0; nd < 2; ++nd) {
                    int d = nd * 8 + 2 * lc;
                    float2 qv1 = *(const float2*)&Q[qrow * 16 + d];
                    float2 qv2 = *(const float2*)&Q[(qrow + 8) * 16 + d];
                    if (d < 13)     o1[d]     = qv1.x + dacc[m][nd][0] * iTA;
                    if (d + 1 < 13) o1[d + 1] = qv1.y + dacc[m][nd][1] * iTA;
                    if (d < 13)     o2[d]     = qv2.x + dacc[m][nd][2] * iTB;
                    if (d + 1 < 13) o2[d + 1] = qv2.y + dacc[m][nd][3] * iTB;
                }
            }
        }

        if (tid == 0) s_next = atomicAdd(&g_ctr, 1);
        __syncthreads();
        u = s_next;
    }
}

// ---------------------------------------------------------------------------
// Pooled tokens: 8-way row split per (b, tok) + smem reduce.
// ---------------------------------------------------------------------------
__global__ void __launch_bounds__(640) mean_kernel(const float* __restrict__ x,
                                                   const float* __restrict__ out) {
    __shared__ float red[8][78];
    int b = blockIdx.x, tok = blockIdx.y, t = threadIdx.x;
    if (t < 624) {
        int g = t / 78, c = t % 78;
        float s = 0.f;
        if (tok == 0) {
            const float* p = x + (size_t)b * 1024 * 78 + c;
            for (int i = g; i < 1024; i += 8) s += p[(size_t)i * 78];
        } else {
            int r0 = (tok == 1) ? 0 : 2048;
            const float* p = out + ((size_t)b * OUT_ROWS + r0) * 78 + c;
            for (int i = g; i < 2048; i += 8) s += p[(size_t)i * 78];
        }
        red[g][c] = s;
    }
    __syncthreads();
    if (t < 78) {
        float tot = 0.f;
        #pragma unroll
        for (int g = 0; g < 8; ++g) tot += red[g][t];
        g_tok[(b * 3 + tok) * 78 + t] = tot * (1.f / 1024.f);
    }
}

// ---------------------------------------------------------------------------
// Tiny 3-token MHSA on pooled tokens -> output rows 4096..4098.
// ---------------------------------------------------------------------------
__global__ void __launch_bounds__(704) fused_kernel(const float* __restrict__ Wq,
                                                    const float* __restrict__ Wk,
                                                    const float* __restrict__ Wv,
                                                    float* __restrict__ out) {
    __shared__ float tok[3][78];
    __shared__ float qs[3][78], ks[3][78], vs[3][78];
    __shared__ float ps[6][3][3];
    int b = blockIdx.x, t = threadIdx.x;

    for (int idx = t; idx < 234; idx += 704) tok[idx / 78][idx % 78] = g_tok[b * 234 + idx];
    __syncthreads();

    if (t < 702) {
        int comp = t / 234, rem = t % 234, i = rem / 78, c = rem % 78;
        const float* W = (comp == 0) ? Wq : ((comp == 1) ? Wk : Wv);
        float a = 0.f;
        #pragma unroll 13
        for (int k = 0; k < 78; ++k) a = fmaf(tok[i][k], __ldg(&W[k * 78 + c]), a);
        float (*dst)[78] = (comp == 0) ? qs : ((comp == 1) ? ks : vs);
        dst[i][c] = a;
    }
    __syncthreads();

    if (t < 54) {
        int h = t / 9, rem = t % 9, i = rem / 3, j = rem % 3;
        float s = 0.f;
        #pragma unroll
        for (int d = 0; d < 13; ++d) s = fmaf(qs[i][h * 13 + d], ks[j][h * 13 + d], s);
        ps[h][i][j] = s * SCALE;
    }
    __syncthreads();

    if (t < 18) {
        int h = t / 3, i = t % 3;
        float a = ps[h][i][0], bb = ps[h][i][1], c = ps[h][i][2];
        float mx = fmaxf(a, fmaxf(bb, c));
        float ea = ex2((a - mx) * L2E), eb = ex2((bb - mx) * L2E), ec = ex2((c - mx) * L2E);
        float inv = 1.f / (ea + eb + ec);
        ps[h][i][0] = ea * inv; ps[h][i][1] = eb * inv; ps[h][i][2] = ec * inv;
    }
    __syncthreads();

    if (t < 78) {
        int h = t / 13;
        #pragma unroll
        for (int i = 0; i < 3; ++i) {
            float o = ps[h][i][0] * vs[0][t] + ps[h][i][1] * vs[1][t] + ps[h][i][2] * vs[2][t];
            out[((size_t)b * OUT_ROWS + 4096 + i) * 78 + t] = o;
        }
    }
}

// ---------------------------------------------------------------------------
extern "C" void kernel_launch(void* const* d_in, const int* in_sizes, int n_in,
                              void* d_out, int out_size) {
    PtrPack p;
    p.x = (const float*)d_in[0];
    p.y = (const float*)d_in[1];
    p.z = (const float*)d_in[2];
    const int widx[12] = {5, 8, 11, 14,   // Q: tv, ta, ctv, cta
                          6, 9, 12, 15,   // K
                          7, 10, 13, 16}; // V
    for (int i = 0; i < 12; ++i) p.W[i] = (const float*)d_in[widx[i]];
    float* out = (float*)d_out;

    proj_kernel<<<dim3(128, 12), 320>>>(p);
    attn_kernel<<<NBLK, 256>>>(out);
    mean_kernel<<<dim3(8, 3), 640>>>((const float*)d_in[0], out);
    fused_kernel<<<8, 704>>>((const float*)d_in[17], (const float*)d_in[18],
                             (const float*)d_in[19], out);
}

// round 15
// speedup vs baseline: 4.3888x; 1.0258x over previous
#include <cuda_runtime.h>
#include <cuda_bf16.h>
#include <cstdint>

#define OUT_ROWS 4099
#define HSTR 16384                 // per-head element stride (1024*16)
#define SCALE 0.2773500981126146f
#define L2E   1.4426950408889634f
#define CQ    (SCALE*L2E)
#define NUNITS 768
#define NBLK 304
#define VSTR 136                   // Vt smem key-stride (bank-conflict-free)
#define ONESBF 0x3F803F80u         // bf16x2 (1.0, 1.0)

// device scratch (zero-initialized; pad dims 13..15 never written)
__device__ float         g_Q [4*8*6*HSTR];   // fp32 [op][b][h][i][16]
__device__ __nv_bfloat16 g_Kb[4*8*6*HSTR];   // bf16 [op][b][h][key][16]
__device__ __nv_bfloat16 g_Vt[4*8*6*HSTR];   // bf16 [op][b][h][dim16][1024] (V^T)
__device__ float g_tok[8*3*78];
__device__ int   g_ctr;

struct PtrPack {
    const float* x; const float* y; const float* z;
    const float* W[12];
};

__device__ __forceinline__ float ex2(float v) {
    float r; asm("ex2.approx.ftz.f32 %0, %1;" : "=f"(r) : "f"(v)); return r;
}
__device__ __forceinline__ uint32_t pbf(float lo, float hi) {   // pack 2 fp32 -> bf16x2 (lo = element0)
    uint32_t r; asm("cvt.rn.bf16x2.f32 %0, %1, %2;" : "=r"(r) : "f"(hi), "f"(lo)); return r;
}
__device__ __forceinline__ void mma_bf16(float d[4], const uint32_t a[4],
                                         uint32_t b0, uint32_t b1) {
    asm volatile("mma.sync.aligned.m16n8k16.row.col.f32.bf16.bf16.f32 "
                 "{%0,%1,%2,%3}, {%4,%5,%6,%7}, {%8,%9}, {%0,%1,%2,%3};"
                 : "+f"(d[0]), "+f"(d[1]), "+f"(d[2]), "+f"(d[3])
                 : "r"(a[0]), "r"(a[1]), "r"(a[2]), "r"(a[3]), "r"(b0), "r"(b1));
}
__device__ __forceinline__ float rsum4(float v) {
    v += __shfl_xor_sync(0xffffffffu, v, 1);
    v += __shfl_xor_sync(0xffffffffu, v, 2);
    return v;
}

// ---------------------------------------------------------------------------
// Projections -> g_Q (fp32 padded), g_Kb (bf16 row-major), g_Vt (bf16 V^T).
// Also resets the attention work counter.
// ---------------------------------------------------------------------------
__global__ void __launch_bounds__(320) proj_kernel(PtrPack p) {
    int pid = blockIdx.y;
    const float* src = (pid < 4) ? p.x : (((pid & 1) == 0) ? p.y : p.z);
    const float* W = p.W[pid];

    __shared__ float Ws[78][80];
    __shared__ float in_s[64][80];
    int tid = threadIdx.x;
    int row0 = blockIdx.x * 64;

    if (pid == 0 && blockIdx.x == 0 && tid == 0) g_ctr = NBLK;

    for (int idx = tid; idx < 78 * 80; idx += 320) {
        int k = idx / 80, c = idx % 80;
        Ws[k][c] = (c < 78) ? W[k * 78 + c] : 0.f;
    }
    for (int idx = tid; idx < 64 * 80; idx += 320) {
        int r = idx / 80, k = idx % 80;
        in_s[r][k] = (k < 78) ? src[(row0 + r) * 78 + k] : 0.f;
    }
    __syncthreads();

    int r0 = (tid / 20) * 4;
    int c0 = (tid % 20) * 4;
    float acc[4][4] = {};
    #pragma unroll 2
    for (int k = 0; k < 78; ++k) {
        float4 w = *(const float4*)&Ws[k][c0];
        #pragma unroll
        for (int i = 0; i < 4; ++i) {
            float a = in_s[r0 + i][k];
            acc[i][0] = fmaf(a, w.x, acc[i][0]);
            acc[i][1] = fmaf(a, w.y, acc[i][1]);
            acc[i][2] = fmaf(a, w.z, acc[i][2]);
            acc[i][3] = fmaf(a, w.w, acc[i][3]);
        }
    }
    int opi = pid & 3;
    #pragma unroll
    for (int i = 0; i < 4; ++i) {
        int rg = row0 + r0 + i;
        int bb = rg >> 10, ii = rg & 1023;
        #pragma unroll
        for (int j = 0; j < 4; ++j) {
            int c = c0 + j;
            if (c < 78) {
                int h = c / 13, dd = c % 13;
                int base = ((opi * 8 + bb) * 6 + h) * HSTR;
                if (pid < 4)       g_Q [base + ii * 16 + dd] = acc[i][j];
                else if (pid < 8)  g_Kb[base + ii * 16 + dd] = __float2bfloat16(acc[i][j]);
                else               g_Vt[base + dd * 1024 + ii] = __float2bfloat16(acc[i][j]);
            }
        }
    }
}

// ---------------------------------------------------------------------------
// Tensor-core attention. 768 units = (op,b,h,quarter). CTA = 256 thr = 8 warps,
// warp = 32 queries = 2 x m16 tiles; keys looped in 8 tiles of 128.
// Cross: 1 pass, 1 ex2/visit. Contrastive: SINGLE pass via 2nd-order Taylor
// of exp(-p): out = q + (A0 - A1/Z + A2/(2Z^2)) / (1023 + Z2/(2Z^2)),
// where A0=SUM v, A1=SUM e^s v, A2=SUM e^{2s} v, e^{2s}=(e^s)^2 (no 2nd ex2).
// ---------------------------------------------------------------------------
__global__ void __launch_bounds__(256, 2) attn_kernel(float* __restrict__ out) {
    __shared__ __nv_bfloat16 Kt[128 * 16];    // [key][dim]
    __shared__ __nv_bfloat16 Vt[16 * VSTR];   // [dim][key], padded
    __shared__ int s_next;
    int tid = threadIdx.x;
    int lane = tid & 31;
    int warp = tid >> 5;
    int lq = lane >> 2;          // row-in-tile 0..7
    int lc = lane & 3;           // col group 0..3
    int u = blockIdx.x;

    while (u < NUNITS) {
        int quarter = u & 3;
        int rest = u >> 2;             // 0..191
        int op = (rest / 48) ^ 2;      // contrastive units first
        int bh = rest % 48;
        int b = bh / 6, h = bh % 6;
        int base = ((op * 8 + b) * 6 + h) * HSTR;
        const float* Q = g_Q + base;
        const __nv_bfloat16* Kg = g_Kb + base;
        const __nv_bfloat16* Vg = g_Vt + base;
        int q0 = quarter * 256 + warp * 32;

        // ---- Q A-fragments (2 m16 tiles), CQ folded, bf16 ----
        uint32_t qa[2][4];
        #pragma unroll
        for (int m = 0; m < 2; ++m) {
            int row = q0 + m * 16 + lq;
            int col = 2 * lc;
            float2 v0 = *(const float2*)&Q[row * 16 + col];
            float2 v1 = *(const float2*)&Q[(row + 8) * 16 + col];
            float2 v2 = *(const float2*)&Q[row * 16 + col + 8];
            float2 v3 = *(const float2*)&Q[(row + 8) * 16 + col + 8];
            qa[m][0] = pbf(v0.x * CQ, v0.y * CQ);
            qa[m][1] = pbf(v1.x * CQ, v1.y * CQ);
            qa[m][2] = pbf(v2.x * CQ, v2.y * CQ);
            qa[m][3] = pbf(v3.x * CQ, v3.y * CQ);
        }

        int rowoff = (op == 0) ? 0 : (op == 1 ? 2048 : (op == 2 ? 1024 : 3072));

        if (op < 2) {
            // ================= cross attention, single pass =================
            float dacc[2][2][4] = {};
            float zz[2][2] = {};
            for (int t = 0; t < 8; ++t) {
                __syncthreads();
                ((uint4*)Kt)[tid] = ((const uint4*)(Kg + t * 2048))[tid];
                {
                    int r = tid >> 4, c = tid & 15;
                    uint4 v = *(const uint4*)(Vg + r * 1024 + t * 128 + c * 8);
                    *(uint4*)&Vt[r * VSTR + c * 8] = v;
                }
                __syncthreads();
                #pragma unroll 2
                for (int kc = 0; kc < 8; ++kc) {
                    int n0 = kc * 16;
                    float sD[2][2][4] = {};
                    #pragma unroll
                    for (int hf = 0; hf < 2; ++hf) {
                        int nn = n0 + hf * 8;
                        uint32_t b0 = *(const uint32_t*)&Kt[(nn + lq) * 16 + 2 * lc];
                        uint32_t b1 = *(const uint32_t*)&Kt[(nn + lq) * 16 + 2 * lc + 8];
                        mma_bf16(sD[0][hf], qa[0], b0, b1);
                        mma_bf16(sD[1][hf], qa[1], b0, b1);
                    }
                    uint32_t pa[2][4];
                    #pragma unroll
                    for (int m = 0; m < 2; ++m) {
                        #pragma unroll
                        for (int hf = 0; hf < 2; ++hf) {
                            float e0 = ex2(sD[m][hf][0]);
                            float e1 = ex2(sD[m][hf][1]);
                            float e2 = ex2(sD[m][hf][2]);
                            float e3 = ex2(sD[m][hf][3]);
                            zz[m][0] += e0 + e1;
                            zz[m][1] += e2 + e3;
                            pa[m][hf * 2]     = pbf(e0, e1);
                            pa[m][hf * 2 + 1] = pbf(e2, e3);
                        }
                    }
                    #pragma unroll
                    for (int nd = 0; nd < 2; ++nd) {
                        uint32_t vb0 = *(const uint32_t*)&Vt[(nd * 8 + lq) * VSTR + n0 + 2 * lc];
                        uint32_t vb1 = *(const uint32_t*)&Vt[(nd * 8 + lq) * VSTR + n0 + 2 * lc + 8];
                        mma_bf16(dacc[0][nd], pa[0], vb0, vb1);
                        mma_bf16(dacc[1][nd], pa[1], vb0, vb1);
                    }
                }
            }
            #pragma unroll
            for (int m = 0; m < 2; ++m) {
                float izA = 1.f / rsum4(zz[m][0]);
                float izB = 1.f / rsum4(zz[m][1]);
                int row = rowoff + q0 + m * 16 + lq;
                float* o1 = out + ((size_t)b * OUT_ROWS + row) * 78 + h * 13;
                float* o2 = o1 + (size_t)8 * 78;
                #pragma unroll
                for (int nd = 0; nd < 2; ++nd) {
                    int d = nd * 8 + 2 * lc;
                    if (d < 13)     o1[d]     = dacc[m][nd][0] * izA;
                    if (d + 1 < 13) o1[d + 1] = dacc[m][nd][1] * izA;
                    if (d < 13)     o2[d]     = dacc[m][nd][2] * izB;
                    if (d + 1 < 13) o2[d + 1] = dacc[m][nd][3] * izB;
                }
            }
        } else {
            // ======== contrastive, SINGLE pass (Taylor exp(-p)) ========
            float d0[2][2][4] = {};   // A0: SUM v
            float d1[2][2][4] = {};   // A1: SUM e^s v
            float d2[2][2][4] = {};   // A2: SUM e^{2s} v
            float zz1[2][2] = {};     // Z  = SUM e^s
            float zz2[2][2] = {};     // Z2 = SUM e^{2s}
            const uint32_t onesA[4] = {ONESBF, ONESBF, ONESBF, ONESBF};

            for (int t = 0; t < 8; ++t) {
                __syncthreads();
                ((uint4*)Kt)[tid] = ((const uint4*)(Kg + t * 2048))[tid];
                {
                    int r = tid >> 4, c = tid & 15;
                    uint4 v = *(const uint4*)(Vg + r * 1024 + t * 128 + c * 8);
                    *(uint4*)&Vt[r * VSTR + c * 8] = v;
                }
                __syncthreads();
                #pragma unroll 2
                for (int kc = 0; kc < 8; ++kc) {
                    int n0 = kc * 16;
                    float sD[2][2][4] = {};
                    #pragma unroll
                    for (int hf = 0; hf < 2; ++hf) {
                        int nn = n0 + hf * 8;
                        uint32_t b0 = *(const uint32_t*)&Kt[(nn + lq) * 16 + 2 * lc];
                        uint32_t b1 = *(const uint32_t*)&Kt[(nn + lq) * 16 + 2 * lc + 8];
                        mma_bf16(sD[0][hf], qa[0], b0, b1);
                        mma_bf16(sD[1][hf], qa[1], b0, b1);
                    }
                    uint32_t pa1[2][4], pa2[2][4];
                    #pragma unroll
                    for (int m = 0; m < 2; ++m) {
                        #pragma unroll
                        for (int hf = 0; hf < 2; ++hf) {
                            float e0 = ex2(sD[m][hf][0]);
                            float e1 = ex2(sD[m][hf][1]);
                            float e2 = ex2(sD[m][hf][2]);
                            float e3 = ex2(sD[m][hf][3]);
                            float q0s = e0 * e0, q1s = e1 * e1;
                            float q2s = e2 * e2, q3s = e3 * e3;
                            zz1[m][0] += e0 + e1;
                            zz1[m][1] += e2 + e3;
                            zz2[m][0] += q0s + q1s;
                            zz2[m][1] += q2s + q3s;
                            pa1[m][hf * 2]     = pbf(e0, e1);
                            pa1[m][hf * 2 + 1] = pbf(e2, e3);
                            pa2[m][hf * 2]     = pbf(q0s, q1s);
                            pa2[m][hf * 2 + 1] = pbf(q2s, q3s);
                        }
                    }
                    #pragma unroll
                    for (int nd = 0; nd < 2; ++nd) {
                        uint32_t vb0 = *(const uint32_t*)&Vt[(nd * 8 + lq) * VSTR + n0 + 2 * lc];
                        uint32_t vb1 = *(const uint32_t*)&Vt[(nd * 8 + lq) * VSTR + n0 + 2 * lc + 8];
                        mma_bf16(d0[0][nd], onesA,  vb0, vb1);
                        mma_bf16(d0[1][nd], onesA,  vb0, vb1);
                        mma_bf16(d1[0][nd], pa1[0], vb0, vb1);
                        mma_bf16(d1[1][nd], pa1[1], vb0, vb1);
                        mma_bf16(d2[0][nd], pa2[0], vb0, vb1);
                        mma_bf16(d2[1][nd], pa2[1], vb0, vb1);
                    }
                }
            }
            #pragma unroll
            for (int m = 0; m < 2; ++m) {
                float ZA = rsum4(zz1[m][0]);
                float ZB = rsum4(zz1[m][1]);
                float Z2A = rsum4(zz2[m][0]);
                float Z2B = rsum4(zz2[m][1]);
                float izA = 1.f / ZA, izB = 1.f / ZB;
                float cA = 0.5f * izA * izA;      // 1/(2Z^2)
                float cB = 0.5f * izB * izB;
                float iTA = 1.f / (1023.f + Z2A * cA);
                float iTB = 1.f / (1023.f + Z2B * cB);
                int qrow = q0 + m * 16 + lq;
                int row = rowoff + qrow;
                float* o1 = out + ((size_t)b * OUT_ROWS + row) * 78 + h * 13;
                float* o2 = o1 + (size_t)8 * 78;
                #pragma unroll
                for (int nd = 0; nd < 2; ++nd) {
                    int d = nd * 8 + 2 * lc;
                    float2 qv1 = *(const float2*)&Q[qrow * 16 + d];
                    float2 qv2 = *(const float2*)&Q[(qrow + 8) * 16 + d];
                    float n0v = d0[m][nd][0] - d1[m][nd][0] * izA + d2[m][nd][0] * cA;
                    float n1v = d0[m][nd][1] - d1[m][nd][1] * izA + d2[m][nd][1] * cA;
                    float n2v = d0[m][nd][2] - d1[m][nd][2] * izB + d2[m][nd][2] * cB;
                    float n3v = d0[m][nd][3] - d1[m][nd][3] * izB + d2[m][nd][3] * cB;
                    if (d < 13)     o1[d]     = qv1.x + n0v * iTA;
                    if (d + 1 < 13) o1[d + 1] = qv1.y + n1v * iTA;
                    if (d < 13)     o2[d]     = qv2.x + n2v * iTB;
                    if (d + 1 < 13) o2[d + 1] = qv2.y + n3v * iTB;
                }
            }
        }

        if (tid == 0) s_next = atomicAdd(&g_ctr, 1);
        __syncthreads();
        u = s_next;
    }
}

// ---------------------------------------------------------------------------
// Pooled tokens: 8-way row split per (b, tok) + smem reduce.
// ---------------------------------------------------------------------------
__global__ void __launch_bounds__(640) mean_kernel(const float* __restrict__ x,
                                                   const float* __restrict__ out) {
    __shared__ float red[8][78];
    int b = blockIdx.x, tok = blockIdx.y, t = threadIdx.x;
    if (t < 624) {
        int g = t / 78, c = t % 78;
        float s = 0.f;
        if (tok == 0) {
            const float* p = x + (size_t)b * 1024 * 78 + c;
            for (int i = g; i < 1024; i += 8) s += p[(size_t)i * 78];
        } else {
            int r0 = (tok == 1) ? 0 : 2048;
            const float* p = out + ((size_t)b * OUT_ROWS + r0) * 78 + c;
            for (int i = g; i < 2048; i += 8) s += p[(size_t)i * 78];
        }
        red[g][c] = s;
    }
    __syncthreads();
    if (t < 78) {
        float tot = 0.f;
        #pragma unroll
        for (int g = 0; g < 8; ++g) tot += red[g][t];
        g_tok[(b * 3 + tok) * 78 + t] = tot * (1.f / 1024.f);
    }
}

// ---------------------------------------------------------------------------
// Tiny 3-token MHSA on pooled tokens -> output rows 4096..4098.
// ---------------------------------------------------------------------------
__global__ void __launch_bounds__(704) fused_kernel(const float* __restrict__ Wq,
                                                    const float* __restrict__ Wk,
                                                    const float* __restrict__ Wv,
                                                    float* __restrict__ out) {
    __shared__ float tok[3][78];
    __shared__ float qs[3][78], ks[3][78], vs[3][78];
    __shared__ float ps[6][3][3];
    int b = blockIdx.x, t = threadIdx.x;

    for (int idx = t; idx < 234; idx += 704) tok[idx / 78][idx % 78] = g_tok[b * 234 + idx];
    __syncthreads();

    if (t < 702) {
        int comp = t / 234, rem = t % 234, i = rem / 78, c = rem % 78;
        const float* W = (comp == 0) ? Wq : ((comp == 1) ? Wk : Wv);
        float a = 0.f;
        #pragma unroll 13
        for (int k = 0; k < 78; ++k) a = fmaf(tok[i][k], __ldg(&W[k * 78 + c]), a);
        float (*dst)[78] = (comp == 0) ? qs : ((comp == 1) ? ks : vs);
        dst[i][c] = a;
    }
    __syncthreads();

    if (t < 54) {
        int h = t / 9, rem = t % 9, i = rem / 3, j = rem % 3;
        float s = 0.f;
        #pragma unroll
        for (int d = 0; d < 13; ++d) s = fmaf(qs[i][h * 13 + d], ks[j][h * 13 + d], s);
        ps[h][i][j] = s * SCALE;
    }
    __syncthreads();

    if (t < 18) {
        int h = t / 3, i = t % 3;
        float a = ps[h][i][0], bb = ps[h][i][1], c = ps[h][i][2];
        float mx = fmaxf(a, fmaxf(bb, c));
        float ea = ex2((a - mx) * L2E), eb = ex2((bb - mx) * L2E), ec = ex2((c - mx) * L2E);
        float inv = 1.f / (ea + eb + ec);
        ps[h][i][0] = ea * inv; ps[h][i][1] = eb * inv; ps[h][i][2] = ec * inv;
    }
    __syncthreads();

    if (t < 78) {
        int h = t / 13;
        #pragma unroll
        for (int i = 0; i < 3; ++i) {
            float o = ps[h][i][0] * vs[0][t] + ps[h][i][1] * vs[1][t] + ps[h][i][2] * vs[2][t];
            out[((size_t)b * OUT_ROWS + 4096 + i) * 78 + t] = o;
        }
    }
}

// ---------------------------------------------------------------------------
extern "C" void kernel_launch(void* const* d_in, const int* in_sizes, int n_in,
                              void* d_out, int out_size) {
    PtrPack p;
    p.x = (const float*)d_in[0];
    p.y = (const float*)d_in[1];
    p.z = (const float*)d_in[2];
    const int widx[12] = {5, 8, 11, 14,   // Q: tv, ta, ctv, cta
                          6, 9, 12, 15,   // K
                          7, 10, 13, 16}; // V
    for (int i = 0; i < 12; ++i) p.W[i] = (const float*)d_in[widx[i]];
    float* out = (float*)d_out;

    proj_kernel<<<dim3(128, 12), 320>>>(p);
    attn_kernel<<<NBLK, 256>>>(out);
    mean_kernel<<<dim3(8, 3), 640>>>((const float*)d_in[0], out);
    fused_kernel<<<8, 704>>>((const float*)d_in[17], (const float*)d_in[18],
                             (const float*)d_in[19], out);
}

// round 16
// speedup vs baseline: 6.4820x; 1.4769x over previous
#include <cuda_runtime.h>
#include <cuda_bf16.h>
#include <cstdint>

#define OUT_ROWS 4099
#define HSTR 16384                 // per-head element stride (1024*16)
#define SCALE 0.2773500981126146f
#define L2E   1.4426950408889634f
#define CQ    (SCALE*L2E)
#define NUNITS 768
#define NBLK 304
#define VSTR 136                   // Vt smem key-stride (bank-conflict-free)
#define WSTR 136                   // W smem k-stride (bank-conflict-free B-frags)
#define ONESBF 0x3F803F80u         // bf16x2 (1.0, 1.0)

// device scratch (zero-initialized; pad dims 13..15 never written)
__device__ float         g_Q [4*8*6*HSTR];   // fp32 [op][b][h][i][16]
__device__ __nv_bfloat16 g_Kb[4*8*6*HSTR];   // bf16 [op][b][h][key][16]
__device__ __nv_bfloat16 g_Vt[4*8*6*HSTR];   // bf16 [op][b][h][dim16][1024] (V^T)
__device__ float g_tok[8*3*78];
__device__ int   g_ctr;

struct PtrPack {
    const float* x; const float* y; const float* z;
    const float* W[12];
};

__device__ __forceinline__ float ex2(float v) {
    float r; asm("ex2.approx.ftz.f32 %0, %1;" : "=f"(r) : "f"(v)); return r;
}
__device__ __forceinline__ uint32_t pbf(float lo, float hi) {   // pack 2 fp32 -> bf16x2 (lo = element0)
    uint32_t r; asm("cvt.rn.bf16x2.f32 %0, %1, %2;" : "=r"(r) : "f"(hi), "f"(lo)); return r;
}
__device__ __forceinline__ void mma_bf16(float d[4], const uint32_t a[4],
                                         uint32_t b0, uint32_t b1) {
    asm volatile("mma.sync.aligned.m16n8k16.row.col.f32.bf16.bf16.f32 "
                 "{%0,%1,%2,%3}, {%4,%5,%6,%7}, {%8,%9}, {%0,%1,%2,%3};"
                 : "+f"(d[0]), "+f"(d[1]), "+f"(d[2]), "+f"(d[3])
                 : "r"(a[0]), "r"(a[1]), "r"(a[2]), "r"(a[3]), "r"(b0), "r"(b1));
}
__device__ __forceinline__ float rsum4(float v) {
    v += __shfl_xor_sync(0xffffffffu, v, 1);
    v += __shfl_xor_sync(0xffffffffu, v, 2);
    return v;
}
// residual of a float2 after bf16x2 rounding (for split-bf16 GEMM)
__device__ __forceinline__ uint32_t presid(float2 v, uint32_t hi) {
    float hx = __uint_as_float(hi << 16);
    float hy = __uint_as_float(hi & 0xFFFF0000u);
    return pbf(v.x - hx, v.y - hy);
}

// ---------------------------------------------------------------------------
// Split-bf16 tensor-core projection: out = src @ W with 3-term compensation
// (hi*Whi + hi*Wlo + lo*Whi), error ~2^-18. Scatters into g_Q / g_Kb / g_Vt.
// Grid (32, 12) x 512 thr; warp = 16 rows x 78 cols, k=78 in 5 steps of 16.
// ---------------------------------------------------------------------------
__device__ __forceinline__ void pstore(int pid, int rg, int c, float v) {
    if (c >= 78) return;
    int h = c / 13, dd = c % 13;
    int bb = rg >> 10, ii = rg & 1023;
    int base = (((pid & 3) * 8 + bb) * 6 + h) * HSTR;
    if (pid < 4)      g_Q [base + ii * 16 + dd] = v;
    else if (pid < 8) g_Kb[base + ii * 16 + dd] = __float2bfloat16(v);
    else              g_Vt[base + dd * 1024 + ii] = __float2bfloat16(v);
}

__global__ void __launch_bounds__(512) proj_kernel(PtrPack p) {
    int pid = blockIdx.y;
    const float* src = (pid < 4) ? p.x : (((pid & 1) == 0) ? p.y : p.z);
    const float* W = p.W[pid];

    __shared__ __nv_bfloat16 Whi[80 * WSTR];   // [c][k] transposed, zero-padded
    __shared__ __nv_bfloat16 Wlo[80 * WSTR];
    int tid = threadIdx.x;

    if (pid == 0 && blockIdx.x == 0 && tid == 0) g_ctr = NBLK;

    // zero both smem arrays (pads must be 0)
    for (int i = tid; i < 80 * WSTR / 8; i += 512) {
        ((uint4*)Whi)[i] = make_uint4(0, 0, 0, 0);
        ((uint4*)Wlo)[i] = make_uint4(0, 0, 0, 0);
    }
    __syncthreads();
    // stage W transposed with hi/lo split
    for (int idx = tid; idx < 78 * 78; idx += 512) {
        int k = idx / 78, c = idx % 78;     // W row-major [k][c]
        float w = W[idx];
        __nv_bfloat16 hb = __float2bfloat16(w);
        Whi[c * WSTR + k] = hb;
        Wlo[c * WSTR + k] = __float2bfloat16(w - __bfloat162float(hb));
    }
    __syncthreads();

    int warp = tid >> 5, lane = tid & 31;
    int lq = lane >> 2, lc = lane & 3;
    int r0 = blockIdx.x * 256 + warp * 16 + lq;

    // A-fragments for all 5 k-steps, hi + residual, held in registers
    uint32_t ahi[5][4], alo[5][4];
    #pragma unroll
    for (int ks = 0; ks < 5; ++ks) {
        int k0 = ks * 16;
        int ca = k0 + 2 * lc;
        int cb = ca + 8;
        float2 v0 = *(const float2*)&src[(size_t)r0 * 78 + ca];
        float2 v1 = *(const float2*)&src[(size_t)(r0 + 8) * 78 + ca];
        float2 v2 = make_float2(0.f, 0.f), v3 = make_float2(0.f, 0.f);
        if (cb < 78) {
            v2 = *(const float2*)&src[(size_t)r0 * 78 + cb];
            v3 = *(const float2*)&src[(size_t)(r0 + 8) * 78 + cb];
        }
        ahi[ks][0] = pbf(v0.x, v0.y);  alo[ks][0] = presid(v0, ahi[ks][0]);
        ahi[ks][1] = pbf(v1.x, v1.y);  alo[ks][1] = presid(v1, ahi[ks][1]);
        ahi[ks][2] = pbf(v2.x, v2.y);  alo[ks][2] = presid(v2, ahi[ks][2]);
        ahi[ks][3] = pbf(v3.x, v3.y);  alo[ks][3] = presid(v3, ahi[ks][3]);
    }

    #pragma unroll
    for (int nt = 0; nt < 10; ++nt) {
        int n0 = nt * 8;
        float d[4] = {};
        #pragma unroll
        for (int ks = 0; ks < 5; ++ks) {
            int k0 = ks * 16;
            const __nv_bfloat16* bh = &Whi[(n0 + lq) * WSTR + k0 + 2 * lc];
            const __nv_bfloat16* bl = &Wlo[(n0 + lq) * WSTR + k0 + 2 * lc];
            uint32_t bh0 = *(const uint32_t*)bh;
            uint32_t bh1 = *(const uint32_t*)(bh + 8);
            uint32_t bl0 = *(const uint32_t*)bl;
            uint32_t bl1 = *(const uint32_t*)(bl + 8);
            mma_bf16(d, ahi[ks], bh0, bh1);
            mma_bf16(d, ahi[ks], bl0, bl1);
            mma_bf16(d, alo[ks], bh0, bh1);
        }
        int c0 = n0 + 2 * lc;
        pstore(pid, r0,     c0,     d[0]);
        pstore(pid, r0,     c0 + 1, d[1]);
        pstore(pid, r0 + 8, c0,     d[2]);
        pstore(pid, r0 + 8, c0 + 1, d[3]);
    }
}

// ---------------------------------------------------------------------------
// Tensor-core attention (unchanged from the 176us kernel). 768 units =
// (op,b,h,quarter). CTA = 256 thr = 8 warps; warp = 32 queries = 2 x m16
// tiles; keys in 8 tiles of 128. Cross: 1 pass. Contrastive: single pass
// via 2nd-order Taylor of exp(-p).
// ---------------------------------------------------------------------------
__global__ void __launch_bounds__(256, 2) attn_kernel(float* __restrict__ out) {
    __shared__ __nv_bfloat16 Kt[128 * 16];    // [key][dim]
    __shared__ __nv_bfloat16 Vt[16 * VSTR];   // [dim][key], padded
    __shared__ int s_next;
    int tid = threadIdx.x;
    int lane = tid & 31;
    int warp = tid >> 5;
    int lq = lane >> 2;          // row-in-tile 0..7
    int lc = lane & 3;           // col group 0..3
    int u = blockIdx.x;

    while (u < NUNITS) {
        int quarter = u & 3;
        int rest = u >> 2;             // 0..191
        int op = (rest / 48) ^ 2;      // contrastive units first
        int bh = rest % 48;
        int b = bh / 6, h = bh % 6;
        int base = ((op * 8 + b) * 6 + h) * HSTR;
        const float* Q = g_Q + base;
        const __nv_bfloat16* Kg = g_Kb + base;
        const __nv_bfloat16* Vg = g_Vt + base;
        int q0 = quarter * 256 + warp * 32;

        // ---- Q A-fragments (2 m16 tiles), CQ folded, bf16 ----
        uint32_t qa[2][4];
        #pragma unroll
        for (int m = 0; m < 2; ++m) {
            int row = q0 + m * 16 + lq;
            int col = 2 * lc;
            float2 v0 = *(const float2*)&Q[row * 16 + col];
            float2 v1 = *(const float2*)&Q[(row + 8) * 16 + col];
            float2 v2 = *(const float2*)&Q[row * 16 + col + 8];
            float2 v3 = *(const float2*)&Q[(row + 8) * 16 + col + 8];
            qa[m][0] = pbf(v0.x * CQ, v0.y * CQ);
            qa[m][1] = pbf(v1.x * CQ, v1.y * CQ);
            qa[m][2] = pbf(v2.x * CQ, v2.y * CQ);
            qa[m][3] = pbf(v3.x * CQ, v3.y * CQ);
        }

        int rowoff = (op == 0) ? 0 : (op == 1 ? 2048 : (op == 2 ? 1024 : 3072));

        if (op < 2) {
            // ================= cross attention, single pass =================
            float dacc[2][2][4] = {};
            float zz[2][2] = {};
            for (int t = 0; t < 8; ++t) {
                __syncthreads();
                ((uint4*)Kt)[tid] = ((const uint4*)(Kg + t * 2048))[tid];
                {
                    int r = tid >> 4, c = tid & 15;
                    uint4 v = *(const uint4*)(Vg + r * 1024 + t * 128 + c * 8);
                    *(uint4*)&Vt[r * VSTR + c * 8] = v;
                }
                __syncthreads();
                #pragma unroll 2
                for (int kc = 0; kc < 8; ++kc) {
                    int n0 = kc * 16;
                    float sD[2][2][4] = {};
                    #pragma unroll
                    for (int hf = 0; hf < 2; ++hf) {
                        int nn = n0 + hf * 8;
                        uint32_t b0 = *(const uint32_t*)&Kt[(nn + lq) * 16 + 2 * lc];
                        uint32_t b1 = *(const uint32_t*)&Kt[(nn + lq) * 16 + 2 * lc + 8];
                        mma_bf16(sD[0][hf], qa[0], b0, b1);
                        mma_bf16(sD[1][hf], qa[1], b0, b1);
                    }
                    uint32_t pa[2][4];
                    #pragma unroll
                    for (int m = 0; m < 2; ++m) {
                        #pragma unroll
                        for (int hf = 0; hf < 2; ++hf) {
                            float e0 = ex2(sD[m][hf][0]);
                            float e1 = ex2(sD[m][hf][1]);
                            float e2 = ex2(sD[m][hf][2]);
                            float e3 = ex2(sD[m][hf][3]);
                            zz[m][0] += e0 + e1;
                            zz[m][1] += e2 + e3;
                            pa[m][hf * 2]     = pbf(e0, e1);
                            pa[m][hf * 2 + 1] = pbf(e2, e3);
                        }
                    }
                    #pragma unroll
                    for (int nd = 0; nd < 2; ++nd) {
                        uint32_t vb0 = *(const uint32_t*)&Vt[(nd * 8 + lq) * VSTR + n0 + 2 * lc];
                        uint32_t vb1 = *(const uint32_t*)&Vt[(nd * 8 + lq) * VSTR + n0 + 2 * lc + 8];
                        mma_bf16(dacc[0][nd], pa[0], vb0, vb1);
                        mma_bf16(dacc[1][nd], pa[1], vb0, vb1);
                    }
                }
            }
            #pragma unroll
            for (int m = 0; m < 2; ++m) {
                float izA = 1.f / rsum4(zz[m][0]);
                float izB = 1.f / rsum4(zz[m][1]);
                int row = rowoff + q0 + m * 16 + lq;
                float* o1 = out + ((size_t)b * OUT_ROWS + row) * 78 + h * 13;
                float* o2 = o1 + (size_t)8 * 78;
                #pragma unroll
                for (int nd = 0; nd < 2; ++nd) {
                    int d = nd * 8 + 2 * lc;
                    if (d < 13)     o1[d]     = dacc[m][nd][0] * izA;
                    if (d + 1 < 13) o1[d + 1] = dacc[m][nd][1] * izA;
                    if (d < 13)     o2[d]     = dacc[m][nd][2] * izB;
                    if (d + 1 < 13) o2[d + 1] = dacc[m][nd][3] * izB;
                }
            }
        } else {
            // ======== contrastive, SINGLE pass (Taylor exp(-p)) ========
            float d0[2][2][4] = {};   // A0: SUM v
            float d1[2][2][4] = {};   // A1: SUM e^s v
            float d2[2][2][4] = {};   // A2: SUM e^{2s} v
            float zz1[2][2] = {};     // Z  = SUM e^s
            float zz2[2][2] = {};     // Z2 = SUM e^{2s}
            const uint32_t onesA[4] = {ONESBF, ONESBF, ONESBF, ONESBF};

            for (int t = 0; t < 8; ++t) {
                __syncthreads();
                ((uint4*)Kt)[tid] = ((const uint4*)(Kg + t * 2048))[tid];
                {
                    int r = tid >> 4, c = tid & 15;
                    uint4 v = *(const uint4*)(Vg + r * 1024 + t * 128 + c * 8);
                    *(uint4*)&Vt[r * VSTR + c * 8] = v;
                }
                __syncthreads();
                #pragma unroll 2
                for (int kc = 0; kc < 8; ++kc) {
                    int n0 = kc * 16;
                    float sD[2][2][4] = {};
                    #pragma unroll
                    for (int hf = 0; hf < 2; ++hf) {
                        int nn = n0 + hf * 8;
                        uint32_t b0 = *(const uint32_t*)&Kt[(nn + lq) * 16 + 2 * lc];
                        uint32_t b1 = *(const uint32_t*)&Kt[(nn + lq) * 16 + 2 * lc + 8];
                        mma_bf16(sD[0][hf], qa[0], b0, b1);
                        mma_bf16(sD[1][hf], qa[1], b0, b1);
                    }
                    uint32_t pa1[2][4], pa2[2][4];
                    #pragma unroll
                    for (int m = 0; m < 2; ++m) {
                        #pragma unroll
                        for (int hf = 0; hf < 2; ++hf) {
                            float e0 = ex2(sD[m][hf][0]);
                            float e1 = ex2(sD[m][hf][1]);
                            float e2 = ex2(sD[m][hf][2]);
                            float e3 = ex2(sD[m][hf][3]);
                            float q0s = e0 * e0, q1s = e1 * e1;
                            float q2s = e2 * e2, q3s = e3 * e3;
                            zz1[m][0] += e0 + e1;
                            zz1[m][1] += e2 + e3;
                            zz2[m][0] += q0s + q1s;
                            zz2[m][1] += q2s + q3s;
                            pa1[m][hf * 2]     = pbf(e0, e1);
                            pa1[m][hf * 2 + 1] = pbf(e2, e3);
                            pa2[m][hf * 2]     = pbf(q0s, q1s);
                            pa2[m][hf * 2 + 1] = pbf(q2s, q3s);
                        }
                    }
                    #pragma unroll
                    for (int nd = 0; nd < 2; ++nd) {
                        uint32_t vb0 = *(const uint32_t*)&Vt[(nd * 8 + lq) * VSTR + n0 + 2 * lc];
                        uint32_t vb1 = *(const uint32_t*)&Vt[(nd * 8 + lq) * VSTR + n0 + 2 * lc + 8];
                        mma_bf16(d0[0][nd], onesA,  vb0, vb1);
                        mma_bf16(d0[1][nd], onesA,  vb0, vb1);
                        mma_bf16(d1[0][nd], pa1[0], vb0, vb1);
                        mma_bf16(d1[1][nd], pa1[1], vb0, vb1);
                        mma_bf16(d2[0][nd], pa2[0], vb0, vb1);
                        mma_bf16(d2[1][nd], pa2[1], vb0, vb1);
                    }
                }
            }
            #pragma unroll
            for (int m = 0; m < 2; ++m) {
                float ZA = rsum4(zz1[m][0]);
                float ZB = rsum4(zz1[m][1]);
                float Z2A = rsum4(zz2[m][0]);
                float Z2B = rsum4(zz2[m][1]);
                float izA = 1.f / ZA, izB = 1.f / ZB;
                float cA = 0.5f * izA * izA;      // 1/(2Z^2)
                float cB = 0.5f * izB * izB;
                float iTA = 1.f / (1023.f + Z2A * cA);
                float iTB = 1.f / (1023.f + Z2B * cB);
                int qrow = q0 + m * 16 + lq;
                int row = rowoff + qrow;
                float* o1 = out + ((size_t)b * OUT_ROWS + row) * 78 + h * 13;
                float* o2 = o1 + (size_t)8 * 78;
                #pragma unroll
                for (int nd = 0; nd < 2; ++nd) {
                    int d = nd * 8 + 2 * lc;
                    float2 qv1 = *(const float2*)&Q[qrow * 16 + d];
                    float2 qv2 = *(const float2*)&Q[(qrow + 8) * 16 + d];
                    float n0v = d0[m][nd][0] - d1[m][nd][0] * izA + d2[m][nd][0] * cA;
                    float n1v = d0[m][nd][1] - d1[m][nd][1] * izA + d2[m][nd][1] * cA;
                    float n2v = d0[m][nd][2] - d1[m][nd][2] * izB + d2[m][nd][2] * cB;
                    float n3v = d0[m][nd][3] - d1[m][nd][3] * izB + d2[m][nd][3] * cB;
                    if (d < 13)     o1[d]     = qv1.x + n0v * iTA;
                    if (d + 1 < 13) o1[d + 1] = qv1.y + n1v * iTA;
                    if (d < 13)     o2[d]     = qv2.x + n2v * iTB;
                    if (d + 1 < 13) o2[d + 1] = qv2.y + n3v * iTB;
                }
            }
        }

        if (tid == 0) s_next = atomicAdd(&g_ctr, 1);
        __syncthreads();
        u = s_next;
    }
}

// ---------------------------------------------------------------------------
// Pooled tokens: 8-way row split per (b, tok) + smem reduce.
// ---------------------------------------------------------------------------
__global__ void __launch_bounds__(640) mean_kernel(const float* __restrict__ x,
                                                   const float* __restrict__ out) {
    __shared__ float red[8][78];
    int b = blockIdx.x, tok = blockIdx.y, t = threadIdx.x;
    if (t < 624) {
        int g = t / 78, c = t % 78;
        float s = 0.f;
        if (tok == 0) {
            const float* p = x + (size_t)b * 1024 * 78 + c;
            for (int i = g; i < 1024; i += 8) s += p[(size_t)i * 78];
        } else {
            int r0 = (tok == 1) ? 0 : 2048;
            const float* p = out + ((size_t)b * OUT_ROWS + r0) * 78 + c;
            for (int i = g; i < 2048; i += 8) s += p[(size_t)i * 78];
        }
        red[g][c] = s;
    }
    __syncthreads();
    if (t < 78) {
        float tot = 0.f;
        #pragma unroll
        for (int g = 0; g < 8; ++g) tot += red[g][t];
        g_tok[(b * 3 + tok) * 78 + t] = tot * (1.f / 1024.f);
    }
}

// ---------------------------------------------------------------------------
// Tiny 3-token MHSA on pooled tokens -> output rows 4096..4098.
// ---------------------------------------------------------------------------
__global__ void __launch_bounds__(704) fused_kernel(const float* __restrict__ Wq,
                                                    const float* __restrict__ Wk,
                                                    const float* __restrict__ Wv,
                                                    float* __restrict__ out) {
    __shared__ float tok[3][78];
    __shared__ float qs[3][78], ks[3][78], vs[3][78];
    __shared__ float ps[6][3][3];
    int b = blockIdx.x, t = threadIdx.x;

    for (int idx = t; idx < 234; idx += 704) tok[idx / 78][idx % 78] = g_tok[b * 234 + idx];
    __syncthreads();

    if (t < 702) {
        int comp = t / 234, rem = t % 234, i = rem / 78, c = rem % 78;
        const float* W = (comp == 0) ? Wq : ((comp == 1) ? Wk : Wv);
        float a = 0.f;
        #pragma unroll 13
        for (int k = 0; k < 78; ++k) a = fmaf(tok[i][k], __ldg(&W[k * 78 + c]), a);
        float (*dst)[78] = (comp == 0) ? qs : ((comp == 1) ? ks : vs);
        dst[i][c] = a;
    }
    __syncthreads();

    if (t < 54) {
        int h = t / 9, rem = t % 9, i = rem / 3, j = rem % 3;
        float s = 0.f;
        #pragma unroll
        for (int d = 0; d < 13; ++d) s = fmaf(qs[i][h * 13 + d], ks[j][h * 13 + d], s);
        ps[h][i][j] = s * SCALE;
    }
    __syncthreads();

    if (t < 18) {
        int h = t / 3, i = t % 3;
        float a = ps[h][i][0], bb = ps[h][i][1], c = ps[h][i][2];
        float mx = fmaxf(a, fmaxf(bb, c));
        float ea = ex2((a - mx) * L2E), eb = ex2((bb - mx) * L2E), ec = ex2((c - mx) * L2E);
        float inv = 1.f / (ea + eb + ec);
        ps[h][i][0] = ea * inv; ps[h][i][1] = eb * inv; ps[h][i][2] = ec * inv;
    }
    __syncthreads();

    if (t < 78) {
        int h = t / 13;
        #pragma unroll
        for (int i = 0; i < 3; ++i) {
            float o = ps[h][i][0] * vs[0][t] + ps[h][i][1] * vs[1][t] + ps[h][i][2] * vs[2][t];
            out[((size_t)b * OUT_ROWS + 4096 + i) * 78 + t] = o;
        }
    }
}

// ---------------------------------------------------------------------------
extern "C" void kernel_launch(void* const* d_in, const int* in_sizes, int n_in,
                              void* d_out, int out_size) {
    PtrPack p;
    p.x = (const float*)d_in[0];
    p.y = (const float*)d_in[1];
    p.z = (const float*)d_in[2];
    const int widx[12] = {5, 8, 11, 14,   // Q: tv, ta, ctv, cta
                          6, 9, 12, 15,   // K
                          7, 10, 13, 16}; // V
    for (int i = 0; i < 12; ++i) p.W[i] = (const float*)d_in[widx[i]];
    float* out = (float*)d_out;

    proj_kernel<<<dim3(32, 12), 512>>>(p);
    attn_kernel<<<NBLK, 256>>>(out);
    mean_kernel<<<dim3(8, 3), 640>>>((const float*)d_in[0], out);
    fused_kernel<<<8, 704>>>((const float*)d_in[17], (const float*)d_in[18],
                             (const float*)d_in[19], out);
}